// round 1
// baseline (speedup 1.0000x reference)
#include <cuda_runtime.h>
#include <math.h>

#define BB 4
#define TT 2048
#define EE 1024
#define HH 16
#define DD 64
#define MROWS (BB * TT)   // 8192

// Scratch (allocation-free rule: __device__ globals)
__device__ float g_q[(size_t)BB * HH * TT * DD];
__device__ float g_k[(size_t)BB * HH * TT * DD];
__device__ float g_v[(size_t)BB * HH * TT * DD];
__device__ float g_att[(size_t)MROWS * EE];

// ---------------------------------------------------------------------------
// SGEMM (NT): C[M,N] = A[M,K] * W[N,K]^T
// 128x128 block tile, BK=8, 256 threads, 8x8 per-thread micro tile.
// MODE 0: plain row-major store to C.
// MODE 1: QKV scatter into g_q/g_k/g_v with [B,H,T,D] layout.
// ---------------------------------------------------------------------------
template <int MODE>
__global__ __launch_bounds__(256, 2)
void sgemm_nt(const float* __restrict__ A, const float* __restrict__ W,
              float* __restrict__ C, int M, int N, int K)
{
    __shared__ float As[8][132];
    __shared__ float Bs[8][132];

    const int tid = threadIdx.x;
    const int m0 = blockIdx.y * 128;
    const int n0 = blockIdx.x * 128;

    const int rload = tid >> 1;          // 0..127
    const int kload = (tid & 1) << 2;    // 0 or 4

    const int tr = (tid >> 4) << 3;      // row base of 8x8 micro tile
    const int tc = (tid & 15) << 3;      // col base

    float acc[8][8];
#pragma unroll
    for (int i = 0; i < 8; ++i)
#pragma unroll
        for (int j = 0; j < 8; ++j) acc[i][j] = 0.f;

    const float* Aptr = A + (size_t)(m0 + rload) * K + kload;
    const float* Wptr = W + (size_t)(n0 + rload) * K + kload;

    for (int k0 = 0; k0 < K; k0 += 8) {
        const float4 av = *(const float4*)(Aptr + k0);
        const float4 bv = *(const float4*)(Wptr + k0);
        As[kload + 0][rload] = av.x;
        As[kload + 1][rload] = av.y;
        As[kload + 2][rload] = av.z;
        As[kload + 3][rload] = av.w;
        Bs[kload + 0][rload] = bv.x;
        Bs[kload + 1][rload] = bv.y;
        Bs[kload + 2][rload] = bv.z;
        Bs[kload + 3][rload] = bv.w;
        __syncthreads();

#pragma unroll
        for (int kk = 0; kk < 8; ++kk) {
            float a[8], b[8];
            *(float4*)(a)     = *(const float4*)&As[kk][tr];
            *(float4*)(a + 4) = *(const float4*)&As[kk][tr + 4];
            *(float4*)(b)     = *(const float4*)&Bs[kk][tc];
            *(float4*)(b + 4) = *(const float4*)&Bs[kk][tc + 4];
#pragma unroll
            for (int i = 0; i < 8; ++i)
#pragma unroll
                for (int j = 0; j < 8; ++j)
                    acc[i][j] = fmaf(a[i], b[j], acc[i][j]);
        }
        __syncthreads();
    }

    if (MODE == 0) {
#pragma unroll
        for (int i = 0; i < 8; ++i) {
            float* cp = C + (size_t)(m0 + tr + i) * N + n0 + tc;
            *(float4*)(cp)     = make_float4(acc[i][0], acc[i][1], acc[i][2], acc[i][3]);
            *(float4*)(cp + 4) = make_float4(acc[i][4], acc[i][5], acc[i][6], acc[i][7]);
        }
    } else {
        // QKV scatter. Columns tc..tc+7 all share (which, head), d contiguous.
        const int n = n0 + tc;
        const int which = n >> 10;         // n / E
        const int rem = n & 1023;          // n % E
        const int h = rem >> 6;            // / D
        const int d = rem & 63;            // % D
        float* base = (which == 0) ? g_q : (which == 1) ? g_k : g_v;
#pragma unroll
        for (int i = 0; i < 8; ++i) {
            const int m = m0 + tr + i;
            const int bidx = m >> 11;      // / T
            const int t = m & 2047;        // % T
            float* dst = base + ((size_t)(bidx * HH + h) * TT + t) * DD + d;
            *(float4*)(dst)     = make_float4(acc[i][0], acc[i][1], acc[i][2], acc[i][3]);
            *(float4*)(dst + 4) = make_float4(acc[i][4], acc[i][5], acc[i][6], acc[i][7]);
        }
    }
}

// ---------------------------------------------------------------------------
// Causal flash attention. One block per (b*h, q-tile of 64 rows).
// 256 threads = 16x16, each owns a 4x4 fragment of the 64x64 S tile and a
// 4x4 fragment of the 64-wide O accumulator. Online softmax with 16-lane
// shuffle reductions. Dynamic SMEM: Q,K,V,P tiles [64][65].
// ---------------------------------------------------------------------------
#define FA_PAD 65
#define FA_SMEM_FLOATS (4 * 64 * FA_PAD)

__global__ __launch_bounds__(256)
void flash_attn()
{
    extern __shared__ float smem[];
    float (*Qs)[FA_PAD] = (float(*)[FA_PAD])(smem);
    float (*Ks)[FA_PAD] = (float(*)[FA_PAD])(smem + 64 * FA_PAD);
    float (*Vs)[FA_PAD] = (float(*)[FA_PAD])(smem + 2 * 64 * FA_PAD);
    float (*Ps)[FA_PAD] = (float(*)[FA_PAD])(smem + 3 * 64 * FA_PAD);

    const int qt = blockIdx.x;       // q tile index 0..31
    const int bh = blockIdx.y;       // 0..63
    const int q0 = qt * 64;
    const float scale = 0.125f;      // D^-0.5

    const int tid = threadIdx.x;
    const int ty = tid >> 4;
    const int tx = tid & 15;
    const int r0 = ty << 2;          // 4 rows
    const int c0 = tx << 2;          // 4 cols

    const float* Qg = g_q + (size_t)bh * TT * DD;
    const float* Kg = g_k + (size_t)bh * TT * DD;
    const float* Vg = g_v + (size_t)bh * TT * DD;

    // Load Q tile (scalar SMEM stores keep pad-65 rows legal)
    for (int i = tid; i < 64 * 16; i += 256) {
        const int r = i >> 4;
        const int c4 = (i & 15) << 2;
        const float4 qv = *(const float4*)&Qg[(size_t)(q0 + r) * DD + c4];
        Qs[r][c4 + 0] = qv.x; Qs[r][c4 + 1] = qv.y;
        Qs[r][c4 + 2] = qv.z; Qs[r][c4 + 3] = qv.w;
    }

    float m_i[4], l_i[4], o[4][4];
#pragma unroll
    for (int i = 0; i < 4; ++i) {
        m_i[i] = -INFINITY;
        l_i[i] = 0.f;
#pragma unroll
        for (int j = 0; j < 4; ++j) o[i][j] = 0.f;
    }

    for (int kt = 0; kt <= qt; ++kt) {
        const int k0 = kt * 64;
        __syncthreads();   // prior PV done (and Q visible on first iter)

        for (int i = tid; i < 64 * 16; i += 256) {
            const int r = i >> 4;
            const int c4 = (i & 15) << 2;
            const float4 kv = *(const float4*)&Kg[(size_t)(k0 + r) * DD + c4];
            Ks[r][c4 + 0] = kv.x; Ks[r][c4 + 1] = kv.y;
            Ks[r][c4 + 2] = kv.z; Ks[r][c4 + 3] = kv.w;
            const float4 vv = *(const float4*)&Vg[(size_t)(k0 + r) * DD + c4];
            Vs[r][c4 + 0] = vv.x; Vs[r][c4 + 1] = vv.y;
            Vs[r][c4 + 2] = vv.z; Vs[r][c4 + 3] = vv.w;
        }
        __syncthreads();

        // S = scale * Q K^T  (4x4 fragment)
        float s[4][4];
#pragma unroll
        for (int i = 0; i < 4; ++i)
#pragma unroll
            for (int j = 0; j < 4; ++j) s[i][j] = 0.f;

#pragma unroll 8
        for (int d = 0; d < 64; ++d) {
            float qv[4], kv[4];
#pragma unroll
            for (int i = 0; i < 4; ++i) qv[i] = Qs[r0 + i][d];
#pragma unroll
            for (int j = 0; j < 4; ++j) kv[j] = Ks[c0 + j][d];
#pragma unroll
            for (int i = 0; i < 4; ++i)
#pragma unroll
                for (int j = 0; j < 4; ++j)
                    s[i][j] = fmaf(qv[i], kv[j], s[i][j]);
        }
#pragma unroll
        for (int i = 0; i < 4; ++i)
#pragma unroll
            for (int j = 0; j < 4; ++j) s[i][j] *= scale;

        // Causal mask only on diagonal tile (k0 == q0 there)
        if (kt == qt) {
#pragma unroll
            for (int i = 0; i < 4; ++i)
#pragma unroll
                for (int j = 0; j < 4; ++j)
                    if ((c0 + j) > (r0 + i)) s[i][j] = -INFINITY;
        }

        // Online softmax update
        float p_sum[4];
#pragma unroll
        for (int i = 0; i < 4; ++i) {
            float rmax = fmaxf(fmaxf(s[i][0], s[i][1]), fmaxf(s[i][2], s[i][3]));
#pragma unroll
            for (int off = 8; off > 0; off >>= 1)
                rmax = fmaxf(rmax, __shfl_xor_sync(0xffffffffu, rmax, off));
            const float m_new = fmaxf(m_i[i], rmax);
            const float alpha = __expf(m_i[i] - m_new);   // 0 when m_i == -inf
            m_i[i] = m_new;

            float rsum = 0.f;
#pragma unroll
            for (int j = 0; j < 4; ++j) {
                const float p = __expf(s[i][j] - m_new);  // masked -> 0
                s[i][j] = p;
                rsum += p;
            }
#pragma unroll
            for (int off = 8; off > 0; off >>= 1)
                rsum += __shfl_xor_sync(0xffffffffu, rsum, off);

            l_i[i] = l_i[i] * alpha + rsum;
#pragma unroll
            for (int j = 0; j < 4; ++j) o[i][j] *= alpha;
            p_sum[i] = rsum;  (void)p_sum;
        }

        // Stage P, then PV accumulate
#pragma unroll
        for (int i = 0; i < 4; ++i)
#pragma unroll
            for (int j = 0; j < 4; ++j)
                Ps[r0 + i][c0 + j] = s[i][j];
        __syncthreads();

#pragma unroll 8
        for (int k = 0; k < 64; ++k) {
            float pv[4], vv[4];
#pragma unroll
            for (int i = 0; i < 4; ++i) pv[i] = Ps[r0 + i][k];
#pragma unroll
            for (int j = 0; j < 4; ++j) vv[j] = Vs[k][c0 + j];
#pragma unroll
            for (int i = 0; i < 4; ++i)
#pragma unroll
                for (int j = 0; j < 4; ++j)
                    o[i][j] = fmaf(pv[i], vv[j], o[i][j]);
        }
    }

    // Epilogue: normalize, write to [B,T,E] with col = h*64 + d
    const int b = bh >> 4;   // / H
    const int h = bh & 15;   // % H
#pragma unroll
    for (int i = 0; i < 4; ++i) {
        const float inv = 1.0f / l_i[i];
        const int t = q0 + r0 + i;
        float* dst = g_att + ((size_t)(b * TT) + t) * EE + h * DD + c0;
        *(float4*)dst = make_float4(o[i][0] * inv, o[i][1] * inv,
                                    o[i][2] * inv, o[i][3] * inv);
    }
}

// ---------------------------------------------------------------------------
extern "C" void kernel_launch(void* const* d_in, const int* in_sizes, int n_in,
                              void* d_out, int out_size)
{
    const float* x    = (const float*)d_in[0];   // [B,T,E]
    const float* Wqkv = (const float*)d_in[1];   // [3E,E]
    const float* Wout = (const float*)d_in[2];   // [E,E]
    float* out = (float*)d_out;                  // [B,T,E]

    void* attp = nullptr;
    cudaGetSymbolAddress(&attp, g_att);

    const int fa_smem_bytes = FA_SMEM_FLOATS * (int)sizeof(float);
    cudaFuncSetAttribute(flash_attn,
                         cudaFuncAttributeMaxDynamicSharedMemorySize,
                         fa_smem_bytes);

    // 1) QKV projection + scatter to [B,H,T,D]
    {
        dim3 grid(3 * EE / 128, MROWS / 128);   // (24, 64)
        sgemm_nt<1><<<grid, 256>>>(x, Wqkv, nullptr, MROWS, 3 * EE, EE);
    }

    // 2) Causal flash attention -> g_att [B,T,E]
    {
        dim3 grid(TT / 64, BB * HH);            // (32, 64)
        flash_attn<<<grid, 256, fa_smem_bytes>>>();
    }

    // 3) Output projection
    {
        dim3 grid(EE / 128, MROWS / 128);       // (8, 64)
        sgemm_nt<0><<<grid, 256>>>((const float*)attp, Wout, out, MROWS, EE, EE);
    }
}

// round 2
// speedup vs baseline: 2.0839x; 2.0839x over previous
#include <cuda_runtime.h>
#include <math.h>
#include <stdint.h>

#define BB 4
#define TT 2048
#define EE 1024
#define HH 16
#define DD 64
#define MROWS (BB * TT)   // 8192

// Scratch (allocation-free rule: __device__ globals)
__device__ float g_q[(size_t)BB * HH * TT * DD];
__device__ float g_k[(size_t)BB * HH * TT * DD];
__device__ float g_v[(size_t)BB * HH * TT * DD];
__device__ float g_att[(size_t)MROWS * EE];

// ---------------------------------------------------------------------------
// tf32 helpers
// ---------------------------------------------------------------------------
__device__ __forceinline__ uint32_t f2tf(float f) {
    uint32_t u;
    asm("cvt.rna.tf32.f32 %0, %1;" : "=r"(u) : "f"(f));
    return u;
}

__device__ __forceinline__ void mma_tf32(float c[4],
                                         uint32_t a0, uint32_t a1, uint32_t a2, uint32_t a3,
                                         uint32_t b0, uint32_t b1) {
    asm volatile(
        "mma.sync.aligned.m16n8k8.row.col.f32.tf32.tf32.f32 "
        "{%0,%1,%2,%3}, {%4,%5,%6,%7}, {%8,%9}, {%0,%1,%2,%3};\n"
        : "+f"(c[0]), "+f"(c[1]), "+f"(c[2]), "+f"(c[3])
        : "r"(a0), "r"(a1), "r"(a2), "r"(a3), "r"(b0), "r"(b1));
}

// ---------------------------------------------------------------------------
// tf32 GEMM (NT): C[M,N] = A[M,K] * W[N,K]^T
// 128x128 block tile, BK=32, 256 threads (8 warps: 4 in M x 2 in N),
// warp tile 32x64, mma m16n8k8 tf32. Register-staged global prefetch.
// MODE 0: row-major store. MODE 1: QKV scatter to g_q/g_k/g_v [B,H,T,D].
// ---------------------------------------------------------------------------
template <int MODE>
__global__ __launch_bounds__(256, 2)
void gemm_tf32(const float* __restrict__ A, const float* __restrict__ W,
               float* __restrict__ C, int M, int N, int K)
{
    __shared__ uint32_t As[128][36];   // [m][k], pad->bank stride 4: conflict-free
    __shared__ uint32_t Ws[128][36];   // [n][k]

    const int tid = threadIdx.x;
    const int m0 = blockIdx.y * 128;
    const int n0 = blockIdx.x * 128;
    const int wid = tid >> 5, lane = tid & 31;
    const int wm = wid & 3;            // warp row (x32)
    const int wn = wid >> 2;           // warp col (x64)
    const int g = lane >> 2, t = lane & 3;

    // staging: thread loads row ar, 16 cols starting at ac (4 float4)
    const int ar = tid & 127;
    const int ac = (tid >> 7) * 16;
    const float* Ap = A + (size_t)(m0 + ar) * K + ac;
    const float* Wp = W + (size_t)(n0 + ar) * K + ac;

    float4 ra[4], rw[4];
#pragma unroll
    for (int i = 0; i < 4; ++i) {
        ra[i] = *(const float4*)(Ap + i * 4);
        rw[i] = *(const float4*)(Wp + i * 4);
    }

    float acc[2][8][4];
#pragma unroll
    for (int mt = 0; mt < 2; ++mt)
#pragma unroll
        for (int nt = 0; nt < 8; ++nt)
#pragma unroll
            for (int j = 0; j < 4; ++j) acc[mt][nt][j] = 0.f;

    for (int k0 = 0; k0 < K; k0 += 32) {
#pragma unroll
        for (int i = 0; i < 4; ++i) {
            uint4 ua = make_uint4(f2tf(ra[i].x), f2tf(ra[i].y), f2tf(ra[i].z), f2tf(ra[i].w));
            *(uint4*)&As[ar][ac + i * 4] = ua;
            uint4 uw = make_uint4(f2tf(rw[i].x), f2tf(rw[i].y), f2tf(rw[i].z), f2tf(rw[i].w));
            *(uint4*)&Ws[ar][ac + i * 4] = uw;
        }
        __syncthreads();

        if (k0 + 32 < K) {
#pragma unroll
            for (int i = 0; i < 4; ++i) {
                ra[i] = *(const float4*)(Ap + k0 + 32 + i * 4);
                rw[i] = *(const float4*)(Wp + k0 + 32 + i * 4);
            }
        }

#pragma unroll
        for (int ks = 0; ks < 4; ++ks) {
            uint32_t af[2][4];
#pragma unroll
            for (int mt = 0; mt < 2; ++mt) {
                const int r = wm * 32 + mt * 16 + g;
                af[mt][0] = As[r][ks * 8 + t];
                af[mt][1] = As[r + 8][ks * 8 + t];
                af[mt][2] = As[r][ks * 8 + t + 4];
                af[mt][3] = As[r + 8][ks * 8 + t + 4];
            }
            uint32_t bf[8][2];
#pragma unroll
            for (int nt = 0; nt < 8; ++nt) {
                const int r = wn * 64 + nt * 8 + g;
                bf[nt][0] = Ws[r][ks * 8 + t];
                bf[nt][1] = Ws[r][ks * 8 + t + 4];
            }
#pragma unroll
            for (int mt = 0; mt < 2; ++mt)
#pragma unroll
                for (int nt = 0; nt < 8; ++nt)
                    mma_tf32(acc[mt][nt], af[mt][0], af[mt][1], af[mt][2], af[mt][3],
                             bf[nt][0], bf[nt][1]);
        }
        __syncthreads();
    }

    // Epilogue
#pragma unroll
    for (int mt = 0; mt < 2; ++mt) {
#pragma unroll
        for (int nt = 0; nt < 8; ++nt) {
            const int row = m0 + wm * 32 + mt * 16 + g;
            const int col = n0 + wn * 64 + nt * 8 + 2 * t;
            if (MODE == 0) {
                *(float2*)(C + (size_t)row * N + col) =
                    make_float2(acc[mt][nt][0], acc[mt][nt][1]);
                *(float2*)(C + (size_t)(row + 8) * N + col) =
                    make_float2(acc[mt][nt][2], acc[mt][nt][3]);
            } else {
                const int which = col >> 10;
                const int rem = col & 1023;
                const int h = rem >> 6;
                const int d = rem & 63;
                float* base = (which == 0) ? g_q : (which == 1) ? g_k : g_v;
                {
                    const int b = row >> 11, tt = row & 2047;
                    *(float2*)(base + ((size_t)(b * HH + h) * TT + tt) * DD + d) =
                        make_float2(acc[mt][nt][0], acc[mt][nt][1]);
                }
                {
                    const int r2 = row + 8;
                    const int b = r2 >> 11, tt = r2 & 2047;
                    *(float2*)(base + ((size_t)(b * HH + h) * TT + tt) * DD + d) =
                        make_float2(acc[mt][nt][2], acc[mt][nt][3]);
                }
            }
        }
    }
}

// ---------------------------------------------------------------------------
// Causal flash attention, tf32 mma. Block = (bh, q-tile of 128 rows), 256 thr.
// Warp w owns rows [w*16, w*16+16): S and P fragments never cross warps, so
// the P SMEM roundtrip needs only __syncwarp. kv tile = 64 keys.
// ---------------------------------------------------------------------------
#define QP 68   // row pad (floats): stride 68 -> bank stride 4 -> conflict-free frags
#define FA_SMEM_BYTES ((128 + 128 + 64 + 64) * QP * 4)

__global__ __launch_bounds__(256)
void flash_attn_tc()
{
    extern __shared__ uint32_t sm[];
    uint32_t (*Qs)[QP] = (uint32_t(*)[QP])sm;                       // [128][QP] tf32 (pre-scaled)
    uint32_t (*Ps)[QP] = (uint32_t(*)[QP])(sm + 128 * QP);          // [128][QP] tf32 probs
    uint32_t (*Ks)[QP] = (uint32_t(*)[QP])(sm + 2 * 128 * QP);      // [64][QP]  [key][d]
    uint32_t (*Vt)[QP] = (uint32_t(*)[QP])(sm + 2 * 128 * QP + 64 * QP); // [64][QP] [d][key]

    const int qt = gridDim.x - 1 - blockIdx.x;   // long tiles first
    const int bh = blockIdx.y;
    const int q0 = qt * 128;

    const int tid = threadIdx.x;
    const int wid = tid >> 5, lane = tid & 31;
    const int g = lane >> 2, t = lane & 3;
    const int wrow = wid * 16;                    // warp's 16 q rows within tile

    const float* Qg = g_q + (size_t)bh * TT * DD;
    const float* Kg = g_k + (size_t)bh * TT * DD;
    const float* Vg = g_v + (size_t)bh * TT * DD;

    // Stage Q (scaled by D^-0.5), tf32
    {
        const int qr = tid & 127;
        const int qc = (tid >> 7) * 32;
#pragma unroll
        for (int i = 0; i < 8; ++i) {
            const float4 v = *(const float4*)&Qg[(size_t)(q0 + qr) * DD + qc + i * 4];
            uint4 u = make_uint4(f2tf(v.x * 0.125f), f2tf(v.y * 0.125f),
                                 f2tf(v.z * 0.125f), f2tf(v.w * 0.125f));
            *(uint4*)&Qs[qr][qc + i * 4] = u;
        }
    }

    float o[8][4];
#pragma unroll
    for (int nt = 0; nt < 8; ++nt)
#pragma unroll
        for (int j = 0; j < 4; ++j) o[nt][j] = 0.f;
    float m0r = -INFINITY, m1r = -INFINITY, l0 = 0.f, l1 = 0.f;

    const int ktmax = 2 * qt + 1;
    for (int kt = 0; kt <= ktmax; ++kt) {
        const int k0 = kt * 64;
        __syncthreads();   // Q visible (first iter) / prior PV done

        // Stage K [key][d] and V transposed [d][key]
        {
            const int key = tid & 63;
            const int dg = (tid >> 6) * 16;
#pragma unroll
            for (int i = 0; i < 4; ++i) {
                const float4 kv = *(const float4*)&Kg[(size_t)(k0 + key) * DD + dg + i * 4];
                uint4 u = make_uint4(f2tf(kv.x), f2tf(kv.y), f2tf(kv.z), f2tf(kv.w));
                *(uint4*)&Ks[key][dg + i * 4] = u;
                const float4 vv = *(const float4*)&Vg[(size_t)(k0 + key) * DD + dg + i * 4];
                Vt[dg + i * 4 + 0][key] = f2tf(vv.x);
                Vt[dg + i * 4 + 1][key] = f2tf(vv.y);
                Vt[dg + i * 4 + 2][key] = f2tf(vv.z);
                Vt[dg + i * 4 + 3][key] = f2tf(vv.w);
            }
        }
        __syncthreads();

        // Warp-level skip: all this warp's rows masked out by this kv tile?
        if (k0 > q0 + wrow + 15) continue;

        // S = Q K^T (scale pre-folded into Q)
        float s[8][4];
#pragma unroll
        for (int nt = 0; nt < 8; ++nt)
#pragma unroll
            for (int j = 0; j < 4; ++j) s[nt][j] = 0.f;

#pragma unroll
        for (int ks = 0; ks < 8; ++ks) {
            const uint32_t a0 = Qs[wrow + g][ks * 8 + t];
            const uint32_t a1 = Qs[wrow + g + 8][ks * 8 + t];
            const uint32_t a2 = Qs[wrow + g][ks * 8 + t + 4];
            const uint32_t a3 = Qs[wrow + g + 8][ks * 8 + t + 4];
#pragma unroll
            for (int nt = 0; nt < 8; ++nt) {
                const uint32_t b0 = Ks[nt * 8 + g][ks * 8 + t];
                const uint32_t b1 = Ks[nt * 8 + g][ks * 8 + t + 4];
                mma_tf32(s[nt], a0, a1, a2, a3, b0, b1);
            }
        }

        // Causal mask (only possible on the last two tiles of this q-tile)
        if (kt >= 2 * qt) {
            const int r0 = q0 + wrow + g;
#pragma unroll
            for (int nt = 0; nt < 8; ++nt) {
                const int kq = k0 + nt * 8 + 2 * t;
                if (kq > r0)     s[nt][0] = -INFINITY;
                if (kq + 1 > r0) s[nt][1] = -INFINITY;
                if (kq > r0 + 8)     s[nt][2] = -INFINITY;
                if (kq + 1 > r0 + 8) s[nt][3] = -INFINITY;
            }
        }

        // Online softmax (rows g and g+8; stats across the 4-lane quad)
        float mx0 = -INFINITY, mx1 = -INFINITY;
#pragma unroll
        for (int nt = 0; nt < 8; ++nt) {
            mx0 = fmaxf(mx0, fmaxf(s[nt][0], s[nt][1]));
            mx1 = fmaxf(mx1, fmaxf(s[nt][2], s[nt][3]));
        }
        mx0 = fmaxf(mx0, __shfl_xor_sync(0xffffffffu, mx0, 1));
        mx0 = fmaxf(mx0, __shfl_xor_sync(0xffffffffu, mx0, 2));
        mx1 = fmaxf(mx1, __shfl_xor_sync(0xffffffffu, mx1, 1));
        mx1 = fmaxf(mx1, __shfl_xor_sync(0xffffffffu, mx1, 2));

        const float mn0 = fmaxf(m0r, mx0);
        const float mn1 = fmaxf(m1r, mx1);
        const float alpha0 = __expf(m0r - mn0);
        const float alpha1 = __expf(m1r - mn1);
        m0r = mn0; m1r = mn1;

        float sum0 = 0.f, sum1 = 0.f;
#pragma unroll
        for (int nt = 0; nt < 8; ++nt) {
            s[nt][0] = __expf(s[nt][0] - mn0);
            s[nt][1] = __expf(s[nt][1] - mn0);
            s[nt][2] = __expf(s[nt][2] - mn1);
            s[nt][3] = __expf(s[nt][3] - mn1);
            sum0 += s[nt][0] + s[nt][1];
            sum1 += s[nt][2] + s[nt][3];
        }
        sum0 += __shfl_xor_sync(0xffffffffu, sum0, 1);
        sum0 += __shfl_xor_sync(0xffffffffu, sum0, 2);
        sum1 += __shfl_xor_sync(0xffffffffu, sum1, 1);
        sum1 += __shfl_xor_sync(0xffffffffu, sum1, 2);

        l0 = l0 * alpha0 + sum0;
        l1 = l1 * alpha1 + sum1;
#pragma unroll
        for (int nt = 0; nt < 8; ++nt) {
            o[nt][0] *= alpha0; o[nt][1] *= alpha0;
            o[nt][2] *= alpha1; o[nt][3] *= alpha1;
        }

        // Stage P (warp-private rows), then PV accumulate
        {
            const int pr = wrow + g;
#pragma unroll
            for (int nt = 0; nt < 8; ++nt) {
                *(uint2*)&Ps[pr][nt * 8 + 2 * t] =
                    make_uint2(f2tf(s[nt][0]), f2tf(s[nt][1]));
                *(uint2*)&Ps[pr + 8][nt * 8 + 2 * t] =
                    make_uint2(f2tf(s[nt][2]), f2tf(s[nt][3]));
            }
        }
        __syncwarp();

#pragma unroll
        for (int ks = 0; ks < 8; ++ks) {
            const uint32_t a0 = Ps[wrow + g][ks * 8 + t];
            const uint32_t a1 = Ps[wrow + g + 8][ks * 8 + t];
            const uint32_t a2 = Ps[wrow + g][ks * 8 + t + 4];
            const uint32_t a3 = Ps[wrow + g + 8][ks * 8 + t + 4];
#pragma unroll
            for (int nt = 0; nt < 8; ++nt) {
                const uint32_t b0 = Vt[nt * 8 + g][ks * 8 + t];
                const uint32_t b1 = Vt[nt * 8 + g][ks * 8 + t + 4];
                mma_tf32(o[nt], a0, a1, a2, a3, b0, b1);
            }
        }
    }

    // Epilogue: normalize and write to g_att [B,T,E], col = h*64 + d
    const float inv0 = 1.0f / l0;
    const float inv1 = 1.0f / l1;
    const int b = bh >> 4, h = bh & 15;
    const int row0 = q0 + wrow + g;
#pragma unroll
    for (int nt = 0; nt < 8; ++nt) {
        const int col = h * 64 + nt * 8 + 2 * t;
        *(float2*)&g_att[((size_t)b * TT + row0) * EE + col] =
            make_float2(o[nt][0] * inv0, o[nt][1] * inv0);
        *(float2*)&g_att[((size_t)b * TT + row0 + 8) * EE + col] =
            make_float2(o[nt][2] * inv1, o[nt][3] * inv1);
    }
}

// ---------------------------------------------------------------------------
extern "C" void kernel_launch(void* const* d_in, const int* in_sizes, int n_in,
                              void* d_out, int out_size)
{
    const float* x    = (const float*)d_in[0];   // [B,T,E]
    const float* Wqkv = (const float*)d_in[1];   // [3E,E]
    const float* Wout = (const float*)d_in[2];   // [E,E]
    float* out = (float*)d_out;                  // [B,T,E]

    void* attp = nullptr;
    cudaGetSymbolAddress(&attp, g_att);

    cudaFuncSetAttribute(flash_attn_tc,
                         cudaFuncAttributeMaxDynamicSharedMemorySize,
                         FA_SMEM_BYTES);

    // 1) QKV projection + scatter to [B,H,T,D]
    {
        dim3 grid(3 * EE / 128, MROWS / 128);   // (24, 64)
        gemm_tf32<1><<<grid, 256>>>(x, Wqkv, nullptr, MROWS, 3 * EE, EE);
    }

    // 2) Causal flash attention -> g_att [B,T,E]
    {
        dim3 grid(TT / 128, BB * HH);           // (16, 64)
        flash_attn_tc<<<grid, 256, FA_SMEM_BYTES>>>();
    }

    // 3) Output projection
    {
        dim3 grid(EE / 128, MROWS / 128);       // (8, 64)
        gemm_tf32<0><<<grid, 256>>>((const float*)attp, Wout, out, MROWS, EE, EE);
    }
}

// round 4
// speedup vs baseline: 3.8043x; 1.8255x over previous
#include <cuda_runtime.h>
#include <math.h>
#include <stdint.h>

#define BB 4
#define TT 2048
#define EE 1024
#define HH 16
#define DD 64
#define MROWS (BB * TT)   // 8192

// ---------------------------------------------------------------------------
// Scratch (__device__ globals; allocation-free rule)
// ---------------------------------------------------------------------------
__device__ float g_xr[(size_t)MROWS * EE];       // x rounded to tf32
__device__ float g_wqkvr[(size_t)3 * EE * EE];   // W_qkv rounded
__device__ float g_woutr[(size_t)EE * EE];       // W_out rounded
__device__ float g_q[(size_t)BB * HH * TT * DD]; // scaled+rounded Q [bh][t][d]
__device__ float g_k[(size_t)BB * HH * TT * DD]; // rounded K [bh][t][d]
__device__ float g_vt[(size_t)BB * HH * DD * TT];// rounded V^T [bh][d][t]
__device__ float g_att[(size_t)MROWS * EE];      // attention out, rounded

// ---------------------------------------------------------------------------
// Baseline-PTX helpers (all sm_80/75 features; NO 'a'-family instructions)
// ---------------------------------------------------------------------------
__device__ __forceinline__ uint32_t f2tf(float f) {
    uint32_t u;
    asm("cvt.rna.tf32.f32 %0, %1;" : "=r"(u) : "f"(f));
    return u;
}

__device__ __forceinline__ void mma_tf32(float c[4],
                                         uint32_t a0, uint32_t a1, uint32_t a2, uint32_t a3,
                                         uint32_t b0, uint32_t b1) {
    asm volatile(
        "mma.sync.aligned.m16n8k8.row.col.f32.tf32.tf32.f32 "
        "{%0,%1,%2,%3}, {%4,%5,%6,%7}, {%8,%9}, {%0,%1,%2,%3};\n"
        : "+f"(c[0]), "+f"(c[1]), "+f"(c[2]), "+f"(c[3])
        : "r"(a0), "r"(a1), "r"(a2), "r"(a3), "r"(b0), "r"(b1));
}

__device__ __forceinline__ void ldsm_x4(uint32_t& d0, uint32_t& d1, uint32_t& d2, uint32_t& d3,
                                        uint32_t addr) {
    asm volatile("ldmatrix.sync.aligned.m8n8.x4.shared.b16 {%0,%1,%2,%3}, [%4];"
                 : "=r"(d0), "=r"(d1), "=r"(d2), "=r"(d3) : "r"(addr));
}

__device__ __forceinline__ uint32_t smem_u32(const void* p) {
    uint32_t a;
    asm("{ .reg .u64 t; cvta.to.shared.u64 t, %1; cvt.u32.u64 %0, t; }"
        : "=r"(a) : "l"(p));
    return a;
}

#define CP16(smem, gptr) \
    asm volatile("cp.async.cg.shared.global [%0], [%1], 16;" :: "r"(smem), "l"(gptr) : "memory")
#define CP_COMMIT() asm volatile("cp.async.commit_group;" ::: "memory")
#define CP_WAIT0()  asm volatile("cp.async.wait_group 0;" ::: "memory")

// ---------------------------------------------------------------------------
// Prep: round f32 -> tf32 bits (stored as f32)
// ---------------------------------------------------------------------------
__global__ void round_tf32(const float4* __restrict__ src, float4* __restrict__ dst, int n4)
{
    int i = blockIdx.x * blockDim.x + threadIdx.x;
    if (i >= n4) return;
    float4 v = src[i];
    dst[i] = make_float4(__uint_as_float(f2tf(v.x)), __uint_as_float(f2tf(v.y)),
                         __uint_as_float(f2tf(v.z)), __uint_as_float(f2tf(v.w)));
}

// ---------------------------------------------------------------------------
// tf32 GEMM (NT): C[M,N] = A[M,K] * W[N,K]^T, K=1024.
// CTA 128x256, BK=32, 8 warps (2m x 4n), warp tile 64x64, ldmatrix fragments,
// 2-stage cp.async double buffer.
// MODE 0: plain row-major store to C (width EE).
// MODE 1: QKV scatter -> g_q (scaled+rounded), g_k (rounded), g_vt (rounded, transposed)
// ---------------------------------------------------------------------------
#define GST 36   // SMEM row stride in words: 144B == 16 mod 128 -> ldsm conflict-free
#define GEMM_SMEM_WORDS (2 * 128 * GST + 2 * 256 * GST)
#define GEMM_SMEM_BYTES (GEMM_SMEM_WORDS * 4)

template <int MODE>
__global__ __launch_bounds__(256, 1)
void gemm_ld(const float* __restrict__ A, const float* __restrict__ W, float* __restrict__ C)
{
    extern __shared__ uint32_t sm[];
    const uint32_t sb = smem_u32(sm);

    const int tid = threadIdx.x, lane = tid & 31, wid = tid >> 5;
    const int wm = wid & 1, wn = wid >> 1;
    const int g = lane >> 2, t = lane & 3;
    const int m0 = blockIdx.y * 128;
    const int n0 = blockIdx.x * 256;

    const float* Ab = A + (size_t)m0 * EE;
    const float* Wb = W + (size_t)n0 * EE;

    float acc[4][8][4];
#pragma unroll
    for (int mt = 0; mt < 4; ++mt)
#pragma unroll
        for (int nt = 0; nt < 8; ++nt)
#pragma unroll
            for (int j = 0; j < 4; ++j) acc[mt][nt][j] = 0.f;

    // stage issue: chunk c into buffer s
    auto issue = [&](int c, int s) {
        const int k0 = c * 32;
        const uint32_t sa = sb + (s * 128 * GST) * 4;
        const uint32_t sw = sb + (2 * 128 * GST + s * 256 * GST) * 4;
#pragma unroll
        for (int i = 0; i < 4; ++i) {               // A: 128x32 = 1024 words /4
            const int idx = tid + i * 256;
            const int r = idx >> 3, c4 = (idx & 7) * 4;
            CP16(sa + (r * GST + c4) * 4, Ab + (size_t)r * EE + k0 + c4);
        }
#pragma unroll
        for (int i = 0; i < 8; ++i) {               // W: 256x32 = 2048 words /4
            const int idx = tid + i * 256;
            const int r = idx >> 3, c4 = (idx & 7) * 4;
            CP16(sw + (r * GST + c4) * 4, Wb + (size_t)r * EE + k0 + c4);
        }
    };

    issue(0, 0);
    CP_COMMIT();

    for (int c = 0; c < 32; ++c) {
        CP_WAIT0();
        __syncthreads();
        if (c + 1 < 32) { issue(c + 1, (c + 1) & 1); CP_COMMIT(); }

        const uint32_t sa = sb + ((c & 1) * 128 * GST) * 4;
        const uint32_t sw = sb + (2 * 128 * GST + (c & 1) * 256 * GST) * 4;

#pragma unroll
        for (int ks = 0; ks < 4; ++ks) {
            const int kc = ks * 8;
            uint32_t a[4][4];
#pragma unroll
            for (int mt = 0; mt < 4; ++mt) {
                const int arow = wm * 64 + mt * 16 + (lane & 7) + ((lane >> 3) & 1) * 8;
                const int acol = kc + (lane >> 4) * 4;
                ldsm_x4(a[mt][0], a[mt][1], a[mt][2], a[mt][3],
                        sa + (arow * GST + acol) * 4);
            }
            uint32_t b[8][2];
#pragma unroll
            for (int j = 0; j < 4; ++j) {
                const int brow = wn * 64 + (j * 2 + ((lane >> 4) & 1)) * 8 + (lane & 7);
                const int bcol = kc + ((lane >> 3) & 1) * 4;
                uint32_t d0, d1, d2, d3;
                ldsm_x4(d0, d1, d2, d3, sw + (brow * GST + bcol) * 4);
                b[2 * j][0] = d0; b[2 * j][1] = d1;
                b[2 * j + 1][0] = d2; b[2 * j + 1][1] = d3;
            }
#pragma unroll
            for (int mt = 0; mt < 4; ++mt)
#pragma unroll
                for (int nt = 0; nt < 8; ++nt)
                    mma_tf32(acc[mt][nt], a[mt][0], a[mt][1], a[mt][2], a[mt][3],
                             b[nt][0], b[nt][1]);
        }
    }

    // Epilogue
#pragma unroll
    for (int mt = 0; mt < 4; ++mt) {
#pragma unroll
        for (int nt = 0; nt < 8; ++nt) {
            const int r0 = m0 + wm * 64 + mt * 16 + g;
            const int col = n0 + wn * 64 + nt * 8 + 2 * t;
            if (MODE == 0) {
                *(float2*)(C + (size_t)r0 * EE + col) =
                    make_float2(acc[mt][nt][0], acc[mt][nt][1]);
                *(float2*)(C + (size_t)(r0 + 8) * EE + col) =
                    make_float2(acc[mt][nt][2], acc[mt][nt][3]);
            } else {
                const int which = col >> 10;
                const int rem = col & 1023;
                const int h = rem >> 6;
                const int d = rem & 63;
#pragma unroll
                for (int half = 0; half < 2; ++half) {
                    const int row = r0 + half * 8;
                    const float v0 = acc[mt][nt][2 * half];
                    const float v1 = acc[mt][nt][2 * half + 1];
                    const int bh = (row >> 11) * HH + h;
                    const int tt = row & 2047;
                    if (which == 0) {
                        *(float2*)(g_q + ((size_t)bh * TT + tt) * DD + d) =
                            make_float2(__uint_as_float(f2tf(v0 * 0.125f)),
                                        __uint_as_float(f2tf(v1 * 0.125f)));
                    } else if (which == 1) {
                        *(float2*)(g_k + ((size_t)bh * TT + tt) * DD + d) =
                            make_float2(__uint_as_float(f2tf(v0)),
                                        __uint_as_float(f2tf(v1)));
                    } else {
                        g_vt[((size_t)bh * DD + d) * TT + tt]     = __uint_as_float(f2tf(v0));
                        g_vt[((size_t)bh * DD + d + 1) * TT + tt] = __uint_as_float(f2tf(v1));
                    }
                }
            }
        }
    }
}

// ---------------------------------------------------------------------------
// Causal flash attention: q-tile 256, kv-tile 64, 8 warps (warp owns 32 rows).
// ldmatrix fragments, cp.async double-buffered K / V^T.
// ---------------------------------------------------------------------------
#define FST 68   // row stride (words): 272B == 16 mod 128 -> ldsm conflict-free
#define QS_OFF 0
#define PS_OFF (256 * FST)
#define KS_OFF (2 * 256 * FST)
#define VT_OFF (KS_OFF + 2 * 64 * FST)
#define FA_SMEM_WORDS (VT_OFF + 2 * 64 * FST)
#define FA_SMEM_BYTES (FA_SMEM_WORDS * 4)

__global__ __launch_bounds__(256, 1)
void flash_attn_ld()
{
    extern __shared__ uint32_t sm[];
    const uint32_t sb = smem_u32(sm);

    const int qt = gridDim.x - 1 - blockIdx.x;   // long tiles first
    const int bh = blockIdx.y;
    const int q0 = qt * 256;

    const int tid = threadIdx.x, lane = tid & 31, wid = tid >> 5;
    const int g = lane >> 2, t = lane & 3;
    const int wrow = wid * 32;

    const float* Qg  = g_q  + (size_t)bh * TT * DD;
    const float* Kg  = g_k  + (size_t)bh * TT * DD;
    const float* Vtg = g_vt + (size_t)bh * DD * TT;

    // issue Q (256x64)
#pragma unroll
    for (int i = 0; i < 16; ++i) {
        const int idx = tid + i * 256;
        const int r = idx >> 4, c4 = (idx & 15) * 4;
        CP16(sb + (QS_OFF + r * FST + c4) * 4, Qg + (size_t)(q0 + r) * DD + c4);
    }
    auto issue_kv = [&](int kt, int s) {
        const int k0 = kt * 64;
#pragma unroll
        for (int i = 0; i < 4; ++i) {
            const int idx = tid + i * 256;
            const int r = idx >> 4, c4 = (idx & 15) * 4;
            CP16(sb + (KS_OFF + s * 64 * FST + r * FST + c4) * 4,
                 Kg + (size_t)(k0 + r) * DD + c4);
            CP16(sb + (VT_OFF + s * 64 * FST + r * FST + c4) * 4,
                 Vtg + (size_t)r * TT + k0 + c4);
        }
    };
    issue_kv(0, 0);
    CP_COMMIT();

    float o[2][8][4];
#pragma unroll
    for (int mt = 0; mt < 2; ++mt)
#pragma unroll
        for (int nt = 0; nt < 8; ++nt)
#pragma unroll
            for (int j = 0; j < 4; ++j) o[mt][nt][j] = 0.f;
    float mr[2][2] = {{-INFINITY, -INFINITY}, {-INFINITY, -INFINITY}};
    float lr[2][2] = {{0.f, 0.f}, {0.f, 0.f}};

    const int ktmax = 4 * qt + 3;
    for (int kt = 0; kt <= ktmax; ++kt) {
        CP_WAIT0();
        __syncthreads();
        if (kt < ktmax) { issue_kv(kt + 1, (kt + 1) & 1); CP_COMMIT(); }

        const int k0 = kt * 64;
        if (k0 > q0 + wrow + 31) continue;   // fully masked for this warp

        const uint32_t ksb = sb + (KS_OFF + (kt & 1) * 64 * FST) * 4;
        const uint32_t vtb = sb + (VT_OFF + (kt & 1) * 64 * FST) * 4;
        const uint32_t qsb = sb + QS_OFF * 4;
        const uint32_t psb = sb + PS_OFF * 4;

        // --- S = Q K^T (scale pre-folded into Q) ---
        float s[2][8][4];
#pragma unroll
        for (int mt = 0; mt < 2; ++mt)
#pragma unroll
            for (int nt = 0; nt < 8; ++nt)
#pragma unroll
                for (int j = 0; j < 4; ++j) s[mt][nt][j] = 0.f;

#pragma unroll
        for (int ks = 0; ks < 8; ++ks) {
            const int kc = ks * 8;
            uint32_t a[2][4];
#pragma unroll
            for (int mt = 0; mt < 2; ++mt) {
                const int arow = wrow + mt * 16 + (lane & 7) + ((lane >> 3) & 1) * 8;
                const int acol = kc + (lane >> 4) * 4;
                ldsm_x4(a[mt][0], a[mt][1], a[mt][2], a[mt][3],
                        qsb + (arow * FST + acol) * 4);
            }
            uint32_t b[8][2];
#pragma unroll
            for (int j = 0; j < 4; ++j) {
                const int brow = (j * 2 + ((lane >> 4) & 1)) * 8 + (lane & 7);
                const int bcol = kc + ((lane >> 3) & 1) * 4;
                uint32_t d0, d1, d2, d3;
                ldsm_x4(d0, d1, d2, d3, ksb + (brow * FST + bcol) * 4);
                b[2 * j][0] = d0; b[2 * j][1] = d1;
                b[2 * j + 1][0] = d2; b[2 * j + 1][1] = d3;
            }
#pragma unroll
            for (int mt = 0; mt < 2; ++mt)
#pragma unroll
                for (int nt = 0; nt < 8; ++nt)
                    mma_tf32(s[mt][nt], a[mt][0], a[mt][1], a[mt][2], a[mt][3],
                             b[nt][0], b[nt][1]);
        }

        // --- causal mask (diagonal region only) ---
        if (k0 + 63 > q0 + wrow) {
#pragma unroll
            for (int mt = 0; mt < 2; ++mt) {
                const int rlo = q0 + wrow + mt * 16 + g;
#pragma unroll
                for (int nt = 0; nt < 8; ++nt) {
                    const int key = k0 + nt * 8 + 2 * t;
                    if (key > rlo)         s[mt][nt][0] = -INFINITY;
                    if (key + 1 > rlo)     s[mt][nt][1] = -INFINITY;
                    if (key > rlo + 8)     s[mt][nt][2] = -INFINITY;
                    if (key + 1 > rlo + 8) s[mt][nt][3] = -INFINITY;
                }
            }
        }

        // --- online softmax + P store (warp-private rows) ---
#pragma unroll
        for (int mt = 0; mt < 2; ++mt) {
            float mx0 = -INFINITY, mx1 = -INFINITY;
#pragma unroll
            for (int nt = 0; nt < 8; ++nt) {
                mx0 = fmaxf(mx0, fmaxf(s[mt][nt][0], s[mt][nt][1]));
                mx1 = fmaxf(mx1, fmaxf(s[mt][nt][2], s[mt][nt][3]));
            }
            mx0 = fmaxf(mx0, __shfl_xor_sync(0xffffffffu, mx0, 1));
            mx0 = fmaxf(mx0, __shfl_xor_sync(0xffffffffu, mx0, 2));
            mx1 = fmaxf(mx1, __shfl_xor_sync(0xffffffffu, mx1, 1));
            mx1 = fmaxf(mx1, __shfl_xor_sync(0xffffffffu, mx1, 2));

            const float mn0 = fmaxf(mr[mt][0], mx0);
            const float mn1 = fmaxf(mr[mt][1], mx1);
            const float al0 = __expf(mr[mt][0] - mn0);
            const float al1 = __expf(mr[mt][1] - mn1);
            mr[mt][0] = mn0; mr[mt][1] = mn1;

            float s0 = 0.f, s1 = 0.f;
#pragma unroll
            for (int nt = 0; nt < 8; ++nt) {
                s[mt][nt][0] = __expf(s[mt][nt][0] - mn0);
                s[mt][nt][1] = __expf(s[mt][nt][1] - mn0);
                s[mt][nt][2] = __expf(s[mt][nt][2] - mn1);
                s[mt][nt][3] = __expf(s[mt][nt][3] - mn1);
                s0 += s[mt][nt][0] + s[mt][nt][1];
                s1 += s[mt][nt][2] + s[mt][nt][3];
            }
            s0 += __shfl_xor_sync(0xffffffffu, s0, 1);
            s0 += __shfl_xor_sync(0xffffffffu, s0, 2);
            s1 += __shfl_xor_sync(0xffffffffu, s1, 1);
            s1 += __shfl_xor_sync(0xffffffffu, s1, 2);

            lr[mt][0] = lr[mt][0] * al0 + s0;
            lr[mt][1] = lr[mt][1] * al1 + s1;
#pragma unroll
            for (int nt = 0; nt < 8; ++nt) {
                o[mt][nt][0] *= al0; o[mt][nt][1] *= al0;
                o[mt][nt][2] *= al1; o[mt][nt][3] *= al1;
            }

            const int pr = wrow + mt * 16 + g;
#pragma unroll
            for (int nt = 0; nt < 8; ++nt) {
                *(uint2*)&sm[PS_OFF + pr * FST + nt * 8 + 2 * t] =
                    make_uint2(f2tf(s[mt][nt][0]), f2tf(s[mt][nt][1]));
                *(uint2*)&sm[PS_OFF + (pr + 8) * FST + nt * 8 + 2 * t] =
                    make_uint2(f2tf(s[mt][nt][2]), f2tf(s[mt][nt][3]));
            }
        }
        __syncwarp();

        // --- O += P V ---
#pragma unroll
        for (int ks = 0; ks < 8; ++ks) {
            const int kc = ks * 8;
            uint32_t a[2][4];
#pragma unroll
            for (int mt = 0; mt < 2; ++mt) {
                const int arow = wrow + mt * 16 + (lane & 7) + ((lane >> 3) & 1) * 8;
                const int acol = kc + (lane >> 4) * 4;
                ldsm_x4(a[mt][0], a[mt][1], a[mt][2], a[mt][3],
                        psb + (arow * FST + acol) * 4);
            }
            uint32_t b[8][2];
#pragma unroll
            for (int j = 0; j < 4; ++j) {
                const int brow = (j * 2 + ((lane >> 4) & 1)) * 8 + (lane & 7);
                const int bcol = kc + ((lane >> 3) & 1) * 4;
                uint32_t d0, d1, d2, d3;
                ldsm_x4(d0, d1, d2, d3, vtb + (brow * FST + bcol) * 4);
                b[2 * j][0] = d0; b[2 * j][1] = d1;
                b[2 * j + 1][0] = d2; b[2 * j + 1][1] = d3;
            }
#pragma unroll
            for (int mt = 0; mt < 2; ++mt)
#pragma unroll
                for (int nt = 0; nt < 8; ++nt)
                    mma_tf32(o[mt][nt], a[mt][0], a[mt][1], a[mt][2], a[mt][3],
                             b[nt][0], b[nt][1]);
        }
    }

    // --- epilogue: normalize, round to tf32, write g_att [B,T,E] ---
    const int b = bh >> 4, h = bh & 15;
#pragma unroll
    for (int mt = 0; mt < 2; ++mt) {
#pragma unroll
        for (int half = 0; half < 2; ++half) {
            const int row = q0 + wrow + mt * 16 + g + half * 8;
            const float inv = 1.0f / lr[mt][half];
#pragma unroll
            for (int nt = 0; nt < 8; ++nt) {
                const int col = h * 64 + nt * 8 + 2 * t;
                const float v0 = o[mt][nt][2 * half] * inv;
                const float v1 = o[mt][nt][2 * half + 1] * inv;
                *(float2*)&g_att[((size_t)b * TT + row) * EE + col] =
                    make_float2(__uint_as_float(f2tf(v0)), __uint_as_float(f2tf(v1)));
            }
        }
    }
}

// ---------------------------------------------------------------------------
// Host
// ---------------------------------------------------------------------------
extern "C" void kernel_launch(void* const* d_in, const int* in_sizes, int n_in,
                              void* d_out, int out_size)
{
    const float* x    = (const float*)d_in[0];   // [B,T,E]
    const float* Wqkv = (const float*)d_in[1];   // [3E,E]
    const float* Wout = (const float*)d_in[2];   // [E,E]
    float* out = (float*)d_out;                  // [B,T,E]

    void *xr, *wqkvr, *woutr, *att;
    cudaGetSymbolAddress(&xr, g_xr);
    cudaGetSymbolAddress(&wqkvr, g_wqkvr);
    cudaGetSymbolAddress(&woutr, g_woutr);
    cudaGetSymbolAddress(&att, g_att);

    cudaFuncSetAttribute(gemm_ld<0>, cudaFuncAttributeMaxDynamicSharedMemorySize, GEMM_SMEM_BYTES);
    cudaFuncSetAttribute(gemm_ld<1>, cudaFuncAttributeMaxDynamicSharedMemorySize, GEMM_SMEM_BYTES);
    cudaFuncSetAttribute(flash_attn_ld, cudaFuncAttributeMaxDynamicSharedMemorySize, FA_SMEM_BYTES);

    // 0) round operands to tf32 once
    {
        int n4 = MROWS * EE / 4;
        round_tf32<<<(n4 + 255) / 256, 256>>>((const float4*)x, (float4*)xr, n4);
        n4 = 3 * EE * EE / 4;
        round_tf32<<<(n4 + 255) / 256, 256>>>((const float4*)Wqkv, (float4*)wqkvr, n4);
        n4 = EE * EE / 4;
        round_tf32<<<(n4 + 255) / 256, 256>>>((const float4*)Wout, (float4*)woutr, n4);
    }

    // 1) QKV projection + scatter (q scaled, v transposed)
    {
        dim3 grid(3 * EE / 256, MROWS / 128);   // (12, 64)
        gemm_ld<1><<<grid, 256, GEMM_SMEM_BYTES>>>((const float*)xr, (const float*)wqkvr, nullptr);
    }

    // 2) Causal flash attention -> g_att
    {
        dim3 grid(TT / 256, BB * HH);           // (8, 64)
        flash_attn_ld<<<grid, 256, FA_SMEM_BYTES>>>();
    }

    // 3) Output projection
    {
        dim3 grid(EE / 256, MROWS / 128);       // (4, 64)
        gemm_ld<0><<<grid, 256, GEMM_SMEM_BYTES>>>((const float*)att, (const float*)woutr, out);
    }
}

// round 5
// speedup vs baseline: 4.6098x; 1.2117x over previous
#include <cuda_runtime.h>
#include <cuda.h>
#include <math.h>
#include <stdint.h>

#define BB 4
#define TT 2048
#define EE 1024
#define HH 16
#define DD 64
#define MROWS (BB * TT)   // 8192

// ---------------------------------------------------------------------------
// Scratch (__device__ globals; allocation-free rule)
// ---------------------------------------------------------------------------
__device__ float g_xr[(size_t)MROWS * EE];       // x rounded to tf32
__device__ float g_wqkvr[(size_t)3 * EE * EE];   // W_qkv rounded
__device__ float g_woutr[(size_t)EE * EE];       // W_out rounded
__device__ float g_q[(size_t)BB * HH * TT * DD]; // scaled+rounded Q [bh][t][d]
__device__ float g_k[(size_t)BB * HH * TT * DD]; // rounded K [bh][t][d]
__device__ float g_vt[(size_t)BB * HH * DD * TT];// rounded V^T [bh][d][t]
__device__ float g_att[(size_t)MROWS * EE];      // attention out, rounded

// ---------------------------------------------------------------------------
// Helpers (all base-PTX for sm_103: mma.sync, ldmatrix, TMA bulk tensor, mbarrier)
// ---------------------------------------------------------------------------
__device__ __forceinline__ uint32_t f2tf(float f) {
    uint32_t u;
    asm("cvt.rna.tf32.f32 %0, %1;" : "=r"(u) : "f"(f));
    return u;
}

__device__ __forceinline__ void mma_tf32(float c[4],
                                         uint32_t a0, uint32_t a1, uint32_t a2, uint32_t a3,
                                         uint32_t b0, uint32_t b1) {
    asm volatile(
        "mma.sync.aligned.m16n8k8.row.col.f32.tf32.tf32.f32 "
        "{%0,%1,%2,%3}, {%4,%5,%6,%7}, {%8,%9}, {%0,%1,%2,%3};\n"
        : "+f"(c[0]), "+f"(c[1]), "+f"(c[2]), "+f"(c[3])
        : "r"(a0), "r"(a1), "r"(a2), "r"(a3), "r"(b0), "r"(b1));
}

__device__ __forceinline__ void ldsm_x4(uint32_t& d0, uint32_t& d1, uint32_t& d2, uint32_t& d3,
                                        uint32_t addr) {
    asm volatile("ldmatrix.sync.aligned.m8n8.x4.shared.b16 {%0,%1,%2,%3}, [%4];"
                 : "=r"(d0), "=r"(d1), "=r"(d2), "=r"(d3) : "r"(addr));
}

__device__ __forceinline__ uint32_t smem_u32(const void* p) {
    uint32_t a;
    asm("{ .reg .u64 t; cvta.to.shared.u64 t, %1; cvt.u32.u64 %0, t; }"
        : "=r"(a) : "l"(p));
    return a;
}

#define MBARRIER_INIT(addr, cnt) \
    asm volatile("mbarrier.init.shared.b64 [%0], %1;" :: "r"((uint32_t)(addr)), "r"((uint32_t)(cnt)) : "memory")

#define MBARRIER_EXPECT_TX(addr, bytes) \
    asm volatile("mbarrier.arrive.expect_tx.shared.b64 _, [%0], %1;" :: "r"((uint32_t)(addr)), "r"((uint32_t)(bytes)) : "memory")

#define MBARRIER_WAIT_PARITY(addr, parity) do {                                   \
    uint32_t _mb = (uint32_t)(addr);                                              \
    uint32_t _ph = (uint32_t)(parity);                                            \
    uint32_t _done;                                                               \
    asm volatile("{\n\t.reg .pred p;\n\t"                                         \
        "mbarrier.try_wait.parity.acquire.cta.shared::cta.b64 p, [%1], %2;\n\t"   \
        "selp.b32 %0, 1, 0, p;\n\t}"                                              \
        : "=r"(_done) : "r"(_mb), "r"(_ph) : "memory");                           \
    if (!_done) {                                                                 \
        asm volatile("{\n\t.reg .pred P1;\n\t"                                    \
            "WAIT_LOOP_%=:\n\t"                                                   \
            "mbarrier.try_wait.parity.acquire.cta.shared::cta.b64 P1, [%0], %1, 0x989680;\n\t" \
            "@P1 bra.uni WAIT_DONE_%=;\n\t"                                       \
            "bra.uni WAIT_LOOP_%=;\n\t"                                           \
            "WAIT_DONE_%=:\n\t}"                                                  \
            :: "r"(_mb), "r"(_ph) : "memory");                                    \
    }                                                                             \
} while (0)

#define TMA_LOAD_2D(smem_addr, map_ptr, cx, cy, mbar) \
    asm volatile("cp.async.bulk.tensor.2d.shared::cta.global.tile.mbarrier::complete_tx::bytes " \
                 "[%0], [%1, {%2, %3}], [%4];" \
                 :: "r"((uint32_t)(smem_addr)), "l"(map_ptr), \
                    "r"((int32_t)(cx)), "r"((int32_t)(cy)), "r"((uint32_t)(mbar)) : "memory")

// ---------------------------------------------------------------------------
// Prep: round f32 -> tf32 bits (stored as f32)
// ---------------------------------------------------------------------------
__global__ void round_tf32(const float4* __restrict__ src, float4* __restrict__ dst, int n4)
{
    int i = blockIdx.x * blockDim.x + threadIdx.x;
    if (i >= n4) return;
    float4 v = src[i];
    dst[i] = make_float4(__uint_as_float(f2tf(v.x)), __uint_as_float(f2tf(v.y)),
                         __uint_as_float(f2tf(v.z)), __uint_as_float(f2tf(v.w)));
}

// ---------------------------------------------------------------------------
// tf32 GEMM (NT): C[M,N] = A[M,K] * W[N,K]^T, K=1024.
// CTA 128x256, BK=32, 8 warps (2m x 4n), warp tile 64x64.
// TMA (SW128) 3-stage pipeline, ldmatrix with swizzle XOR, frag double-buffer.
// MODE 0: plain row-major store. MODE 1: QKV scatter (q scaled, v transposed).
// ---------------------------------------------------------------------------
#define G_NCH 32
#define G_STAGE_BYTES 49152           // A 128x128B + B 256x128B
#define GEMM_SMEM_BYTES (2048 + 3 * G_STAGE_BYTES)

template <int MODE>
__global__ __launch_bounds__(256, 1)
void gemm_tma(const __grid_constant__ CUtensorMap tmA,
              const __grid_constant__ CUtensorMap tmB,
              float* __restrict__ C)
{
    extern __shared__ char smraw[];
    uint32_t sb = smem_u32(smraw);
    sb = (sb + 1023u) & ~1023u;

    const int tid = threadIdx.x, lane = tid & 31, wid = tid >> 5;
    const int wm = wid & 1, wn = wid >> 1;
    const int g = lane >> 2, t = lane & 3;
    const int m0 = blockIdx.y * 128;
    const int n0 = blockIdx.x * 256;

    const uint32_t mb = sb;              // 3 full barriers @ sb, sb+8, sb+16
    const uint32_t st0 = sb + 1024;

    if (tid == 0) {
        MBARRIER_INIT(mb + 0, 1);
        MBARRIER_INIT(mb + 8, 1);
        MBARRIER_INIT(mb + 16, 1);
    }
    __syncthreads();

    auto produce = [&](int c) {
        const int s = c % 3;
        MBARRIER_EXPECT_TX(mb + s * 8, G_STAGE_BYTES);
        const uint32_t sa = st0 + s * G_STAGE_BYTES;
        TMA_LOAD_2D(sa,         &tmA, c * 32, m0, mb + s * 8);
        TMA_LOAD_2D(sa + 16384, &tmB, c * 32, n0, mb + s * 8);
    };

    if (tid == 0) { produce(0); produce(1); }

    float acc[4][8][4];
#pragma unroll
    for (int mt = 0; mt < 4; ++mt)
#pragma unroll
        for (int nt = 0; nt < 8; ++nt)
#pragma unroll
            for (int j = 0; j < 4; ++j) acc[mt][nt][j] = 0.f;

    for (int c = 0; c < G_NCH; ++c) {
        __syncthreads();                               // buf (c+2)%3 free
        if (tid == 0 && c + 2 < G_NCH) produce(c + 2);
        MBARRIER_WAIT_PARITY(mb + (c % 3) * 8, (c / 3) & 1);

        const uint32_t sa = st0 + (c % 3) * G_STAGE_BYTES;
        const uint32_t sw = sa + 16384;

        uint32_t af[2][4][4], bf[2][8][2];
        // fragment load for k-subtile ks into buffer p
        auto ldfrag = [&](int ks, int p) {
            const int kc2 = ks * 2;                    // 16B-chunk base (= kc/4)
#pragma unroll
            for (int mt = 0; mt < 4; ++mt) {
                const int r = wm * 64 + mt * 16 + (lane & 7) + ((lane >> 3) & 1) * 8;
                const int cc = kc2 + (lane >> 4);
                ldsm_x4(af[p][mt][0], af[p][mt][1], af[p][mt][2], af[p][mt][3],
                        sa + r * 128 + ((cc ^ (r & 7)) << 4));
            }
#pragma unroll
            for (int j = 0; j < 4; ++j) {
                const int r = wn * 64 + (j * 2 + ((lane >> 4) & 1)) * 8 + (lane & 7);
                const int cc = kc2 + ((lane >> 3) & 1);
                uint32_t d0, d1, d2, d3;
                ldsm_x4(d0, d1, d2, d3, sw + r * 128 + ((cc ^ (r & 7)) << 4));
                bf[p][2 * j][0] = d0; bf[p][2 * j][1] = d1;
                bf[p][2 * j + 1][0] = d2; bf[p][2 * j + 1][1] = d3;
            }
        };

        ldfrag(0, 0);
#pragma unroll
        for (int ks = 0; ks < 4; ++ks) {
            if (ks < 3) ldfrag(ks + 1, (ks + 1) & 1);
            const int p = ks & 1;
#pragma unroll
            for (int mt = 0; mt < 4; ++mt)
#pragma unroll
                for (int nt = 0; nt < 8; ++nt)
                    mma_tf32(acc[mt][nt], af[p][mt][0], af[p][mt][1], af[p][mt][2], af[p][mt][3],
                             bf[p][nt][0], bf[p][nt][1]);
        }
    }

    // Epilogue
#pragma unroll
    for (int mt = 0; mt < 4; ++mt) {
#pragma unroll
        for (int nt = 0; nt < 8; ++nt) {
            const int r0 = m0 + wm * 64 + mt * 16 + g;
            const int col = n0 + wn * 64 + nt * 8 + 2 * t;
            if (MODE == 0) {
                *(float2*)(C + (size_t)r0 * EE + col) =
                    make_float2(acc[mt][nt][0], acc[mt][nt][1]);
                *(float2*)(C + (size_t)(r0 + 8) * EE + col) =
                    make_float2(acc[mt][nt][2], acc[mt][nt][3]);
            } else {
                const int which = col >> 10;
                const int rem = col & 1023;
                const int h = rem >> 6;
                const int d = rem & 63;
#pragma unroll
                for (int half = 0; half < 2; ++half) {
                    const int row = r0 + half * 8;
                    const float v0 = acc[mt][nt][2 * half];
                    const float v1 = acc[mt][nt][2 * half + 1];
                    const int bh = (row >> 11) * HH + h;
                    const int tt = row & 2047;
                    if (which == 0) {
                        *(float2*)(g_q + ((size_t)bh * TT + tt) * DD + d) =
                            make_float2(__uint_as_float(f2tf(v0 * 0.125f)),
                                        __uint_as_float(f2tf(v1 * 0.125f)));
                    } else if (which == 1) {
                        *(float2*)(g_k + ((size_t)bh * TT + tt) * DD + d) =
                            make_float2(__uint_as_float(f2tf(v0)),
                                        __uint_as_float(f2tf(v1)));
                    } else {
                        g_vt[((size_t)bh * DD + d) * TT + tt]     = __uint_as_float(f2tf(v0));
                        g_vt[((size_t)bh * DD + d + 1) * TT + tt] = __uint_as_float(f2tf(v1));
                    }
                }
            }
        }
    }
}

// ---------------------------------------------------------------------------
// Causal flash attention: q-tile 256, kv-tile 64, 8 warps (warp owns 32 rows).
// TMA-staged Q/K/V^T (SW128 swizzle), ldmatrix, 2-stage kv pipeline.
// SMEM layout (bytes from aligned base):
//   0     : barriers (q_full @0, kv_full @8,16)
//   1024  : Q   (2 regions x 32KB; region = d-half)
//   66560 : P   (2 regions x 32KB; region = key-half)
//   132096: K stages (2 x 16KB; each 2 regions x 8KB, region = d-half)
//   164864: VT stages (2 x 16KB; each 2 regions x 8KB, region = key-half)
// ---------------------------------------------------------------------------
#define FA_Q_OFF   1024
#define FA_P_OFF   (FA_Q_OFF + 65536)
#define FA_K_OFF   (FA_P_OFF + 65536)
#define FA_VT_OFF  (FA_K_OFF + 32768)
#define FA_SMEM_BYTES (FA_VT_OFF + 32768 + 1024)

__global__ __launch_bounds__(256, 1)
void flash_attn_tma(const __grid_constant__ CUtensorMap tmQ,
                    const __grid_constant__ CUtensorMap tmK,
                    const __grid_constant__ CUtensorMap tmVT)
{
    extern __shared__ char smraw[];
    uint32_t sb = smem_u32(smraw);
    sb = (sb + 1023u) & ~1023u;

    const int qt = gridDim.x - 1 - blockIdx.x;   // long tiles first
    const int bh = blockIdx.y;
    const int q0 = qt * 256;

    const int tid = threadIdx.x, lane = tid & 31, wid = tid >> 5;
    const int g = lane >> 2, t = lane & 3;
    const int wrow = wid * 32;

    const uint32_t qb  = sb + FA_Q_OFF;
    const uint32_t pb  = sb + FA_P_OFF;
    const uint32_t kb  = sb + FA_K_OFF;
    const uint32_t vtb = sb + FA_VT_OFF;

    if (tid == 0) {
        MBARRIER_INIT(sb + 0, 1);    // q_full
        MBARRIER_INIT(sb + 8, 1);    // kv_full[0]
        MBARRIER_INIT(sb + 16, 1);   // kv_full[1]
    }
    __syncthreads();

    auto produce_kv = [&](int kt) {
        const int s = kt & 1;
        const int k0 = kt * 64;
        MBARRIER_EXPECT_TX(sb + 8 + s * 8, 32768);
#pragma unroll
        for (int h = 0; h < 2; ++h) {
            TMA_LOAD_2D(kb + s * 16384 + h * 8192, &tmK,
                        h * 32, bh * TT + k0, sb + 8 + s * 8);
            TMA_LOAD_2D(vtb + s * 16384 + h * 8192, &tmVT,
                        k0 + h * 32, bh * 64, sb + 8 + s * 8);
        }
    };

    if (tid == 0) {
        MBARRIER_EXPECT_TX(sb + 0, 65536);
        TMA_LOAD_2D(qb,         &tmQ, 0,  bh * TT + q0, sb + 0);
        TMA_LOAD_2D(qb + 32768, &tmQ, 32, bh * TT + q0, sb + 0);
        produce_kv(0);
    }
    MBARRIER_WAIT_PARITY(sb + 0, 0);

    float o[2][8][4];
#pragma unroll
    for (int mt = 0; mt < 2; ++mt)
#pragma unroll
        for (int nt = 0; nt < 8; ++nt)
#pragma unroll
            for (int j = 0; j < 4; ++j) o[mt][nt][j] = 0.f;
    float mr[2][2] = {{-INFINITY, -INFINITY}, {-INFINITY, -INFINITY}};
    float lr[2][2] = {{0.f, 0.f}, {0.f, 0.f}};

    const int ktmax = 4 * qt + 3;
    for (int kt = 0; kt <= ktmax; ++kt) {
        __syncthreads();                               // kv buf (kt+1)&1 free
        if (tid == 0 && kt + 1 <= ktmax) produce_kv(kt + 1);
        MBARRIER_WAIT_PARITY(sb + 8 + (kt & 1) * 8, (kt >> 1) & 1);

        const int k0 = kt * 64;
        if (k0 > q0 + wrow + 31) continue;             // fully masked for warp

        const uint32_t ks_b = kb + (kt & 1) * 16384;
        const uint32_t vt_b = vtb + (kt & 1) * 16384;

        // --- S = Q K^T (scale pre-folded into Q) ---
        float s[2][8][4];
#pragma unroll
        for (int mt = 0; mt < 2; ++mt)
#pragma unroll
            for (int nt = 0; nt < 8; ++nt)
#pragma unroll
                for (int j = 0; j < 4; ++j) s[mt][nt][j] = 0.f;

#pragma unroll
        for (int ks = 0; ks < 8; ++ks) {
            const int kc2 = ks * 2;                    // 16B-chunk base along d
            uint32_t a[2][4];
#pragma unroll
            for (int mt = 0; mt < 2; ++mt) {
                const int r = wrow + mt * 16 + (lane & 7) + ((lane >> 3) & 1) * 8;
                const int cc = kc2 + (lane >> 4);
                ldsm_x4(a[mt][0], a[mt][1], a[mt][2], a[mt][3],
                        qb + (cc >> 3) * 32768 + r * 128 + ((((cc & 7)) ^ (r & 7)) << 4));
            }
            uint32_t b[8][2];
#pragma unroll
            for (int j = 0; j < 4; ++j) {
                const int r = (j * 2 + ((lane >> 4) & 1)) * 8 + (lane & 7);
                const int cc = kc2 + ((lane >> 3) & 1);
                uint32_t d0, d1, d2, d3;
                ldsm_x4(d0, d1, d2, d3,
                        ks_b + (cc >> 3) * 8192 + r * 128 + ((((cc & 7)) ^ (r & 7)) << 4));
                b[2 * j][0] = d0; b[2 * j][1] = d1;
                b[2 * j + 1][0] = d2; b[2 * j + 1][1] = d3;
            }
#pragma unroll
            for (int mt = 0; mt < 2; ++mt)
#pragma unroll
                for (int nt = 0; nt < 8; ++nt)
                    mma_tf32(s[mt][nt], a[mt][0], a[mt][1], a[mt][2], a[mt][3],
                             b[nt][0], b[nt][1]);
        }

        // --- causal mask (diagonal region only) ---
        if (k0 + 63 > q0 + wrow) {
#pragma unroll
            for (int mt = 0; mt < 2; ++mt) {
                const int rlo = q0 + wrow + mt * 16 + g;
#pragma unroll
                for (int nt = 0; nt < 8; ++nt) {
                    const int key = k0 + nt * 8 + 2 * t;
                    if (key > rlo)         s[mt][nt][0] = -INFINITY;
                    if (key + 1 > rlo)     s[mt][nt][1] = -INFINITY;
                    if (key > rlo + 8)     s[mt][nt][2] = -INFINITY;
                    if (key + 1 > rlo + 8) s[mt][nt][3] = -INFINITY;
                }
            }
        }

        // --- online softmax + P store (warp-private rows, swizzled layout) ---
#pragma unroll
        for (int mt = 0; mt < 2; ++mt) {
            float mx0 = -INFINITY, mx1 = -INFINITY;
#pragma unroll
            for (int nt = 0; nt < 8; ++nt) {
                mx0 = fmaxf(mx0, fmaxf(s[mt][nt][0], s[mt][nt][1]));
                mx1 = fmaxf(mx1, fmaxf(s[mt][nt][2], s[mt][nt][3]));
            }
            mx0 = fmaxf(mx0, __shfl_xor_sync(0xffffffffu, mx0, 1));
            mx0 = fmaxf(mx0, __shfl_xor_sync(0xffffffffu, mx0, 2));
            mx1 = fmaxf(mx1, __shfl_xor_sync(0xffffffffu, mx1, 1));
            mx1 = fmaxf(mx1, __shfl_xor_sync(0xffffffffu, mx1, 2));

            const float mn0 = fmaxf(mr[mt][0], mx0);
            const float mn1 = fmaxf(mr[mt][1], mx1);
            const float al0 = __expf(mr[mt][0] - mn0);
            const float al1 = __expf(mr[mt][1] - mn1);
            mr[mt][0] = mn0; mr[mt][1] = mn1;

            float s0 = 0.f, s1 = 0.f;
#pragma unroll
            for (int nt = 0; nt < 8; ++nt) {
                s[mt][nt][0] = __expf(s[mt][nt][0] - mn0);
                s[mt][nt][1] = __expf(s[mt][nt][1] - mn0);
                s[mt][nt][2] = __expf(s[mt][nt][2] - mn1);
                s[mt][nt][3] = __expf(s[mt][nt][3] - mn1);
                s0 += s[mt][nt][0] + s[mt][nt][1];
                s1 += s[mt][nt][2] + s[mt][nt][3];
            }
            s0 += __shfl_xor_sync(0xffffffffu, s0, 1);
            s0 += __shfl_xor_sync(0xffffffffu, s0, 2);
            s1 += __shfl_xor_sync(0xffffffffu, s1, 1);
            s1 += __shfl_xor_sync(0xffffffffu, s1, 2);

            lr[mt][0] = lr[mt][0] * al0 + s0;
            lr[mt][1] = lr[mt][1] * al1 + s1;
#pragma unroll
            for (int nt = 0; nt < 8; ++nt) {
                o[mt][nt][0] *= al0; o[mt][nt][1] *= al0;
                o[mt][nt][2] *= al1; o[mt][nt][3] *= al1;
            }

#pragma unroll
            for (int half = 0; half < 2; ++half) {
                const int pr = wrow + mt * 16 + g + half * 8;
#pragma unroll
                for (int nt = 0; nt < 8; ++nt) {
                    const int w = nt * 8 + 2 * t;
                    const int cc = w >> 2;
                    const uint32_t addr = pb + (cc >> 3) * 32768 + pr * 128 +
                                          (((cc & 7) ^ (pr & 7)) << 4) + (w & 3) * 4;
                    const uint2 val = make_uint2(f2tf(s[mt][nt][2 * half]),
                                                 f2tf(s[mt][nt][2 * half + 1]));
                    asm volatile("st.shared.v2.b32 [%0], {%1, %2};"
                                 :: "r"(addr), "r"(val.x), "r"(val.y) : "memory");
                }
            }
        }
        __syncwarp();

        // --- O += P V ---
#pragma unroll
        for (int ks = 0; ks < 8; ++ks) {
            const int kc2 = ks * 2;                    // 16B-chunk base along key
            uint32_t a[2][4];
#pragma unroll
            for (int mt = 0; mt < 2; ++mt) {
                const int r = wrow + mt * 16 + (lane & 7) + ((lane >> 3) & 1) * 8;
                const int cc = kc2 + (lane >> 4);
                ldsm_x4(a[mt][0], a[mt][1], a[mt][2], a[mt][3],
                        pb + (cc >> 3) * 32768 + r * 128 + ((((cc & 7)) ^ (r & 7)) << 4));
            }
            uint32_t b[8][2];
#pragma unroll
            for (int j = 0; j < 4; ++j) {
                const int r = (j * 2 + ((lane >> 4) & 1)) * 8 + (lane & 7);
                const int cc = kc2 + ((lane >> 3) & 1);
                uint32_t d0, d1, d2, d3;
                ldsm_x4(d0, d1, d2, d3,
                        vt_b + (cc >> 3) * 8192 + r * 128 + ((((cc & 7)) ^ (r & 7)) << 4));
                b[2 * j][0] = d0; b[2 * j][1] = d1;
                b[2 * j + 1][0] = d2; b[2 * j + 1][1] = d3;
            }
#pragma unroll
            for (int mt = 0; mt < 2; ++mt)
#pragma unroll
                for (int nt = 0; nt < 8; ++nt)
                    mma_tf32(o[mt][nt], a[mt][0], a[mt][1], a[mt][2], a[mt][3],
                             b[nt][0], b[nt][1]);
        }
    }

    // --- epilogue: normalize, round to tf32, write g_att [B,T,E] ---
    const int b = bh >> 4, h = bh & 15;
#pragma unroll
    for (int mt = 0; mt < 2; ++mt) {
#pragma unroll
        for (int half = 0; half < 2; ++half) {
            const int row = q0 + wrow + mt * 16 + g + half * 8;
            const float inv = 1.0f / lr[mt][half];
#pragma unroll
            for (int nt = 0; nt < 8; ++nt) {
                const int col = h * 64 + nt * 8 + 2 * t;
                const float v0 = o[mt][nt][2 * half] * inv;
                const float v1 = o[mt][nt][2 * half + 1] * inv;
                *(float2*)&g_att[((size_t)b * TT + row) * EE + col] =
                    make_float2(__uint_as_float(f2tf(v0)), __uint_as_float(f2tf(v1)));
            }
        }
    }
}

// ---------------------------------------------------------------------------
// Host
// ---------------------------------------------------------------------------
typedef CUresult (*EncodeFn)(CUtensorMap*, CUtensorMapDataType, cuuint32_t, void*,
                             const cuuint64_t*, const cuuint64_t*, const cuuint32_t*,
                             const cuuint32_t*, CUtensorMapInterleave, CUtensorMapSwizzle,
                             CUtensorMapL2promotion, CUtensorMapFloatOOBfill);

static void make_tm(EncodeFn enc, CUtensorMap* tm, void* ptr,
                    uint64_t d0, uint64_t d1, uint32_t b0, uint32_t b1)
{
    cuuint64_t dims[2]    = {d0, d1};
    cuuint64_t strides[1] = {d0 * 4};
    cuuint32_t box[2]     = {b0, b1};
    cuuint32_t estr[2]    = {1, 1};
    enc(tm, CU_TENSOR_MAP_DATA_TYPE_FLOAT32, 2, ptr, dims, strides, box, estr,
        CU_TENSOR_MAP_INTERLEAVE_NONE, CU_TENSOR_MAP_SWIZZLE_128B,
        CU_TENSOR_MAP_L2_PROMOTION_L2_128B, CU_TENSOR_MAP_FLOAT_OOB_FILL_NONE);
}

extern "C" void kernel_launch(void* const* d_in, const int* in_sizes, int n_in,
                              void* d_out, int out_size)
{
    const float* x    = (const float*)d_in[0];   // [B,T,E]
    const float* Wqkv = (const float*)d_in[1];   // [3E,E]
    const float* Wout = (const float*)d_in[2];   // [E,E]
    float* out = (float*)d_out;                  // [B,T,E]

    void *xr, *wqkvr, *woutr, *att, *qp, *kp, *vtp;
    cudaGetSymbolAddress(&xr, g_xr);
    cudaGetSymbolAddress(&wqkvr, g_wqkvr);
    cudaGetSymbolAddress(&woutr, g_woutr);
    cudaGetSymbolAddress(&att, g_att);
    cudaGetSymbolAddress(&qp, g_q);
    cudaGetSymbolAddress(&kp, g_k);
    cudaGetSymbolAddress(&vtp, g_vt);

    void* pf = nullptr;
    cudaDriverEntryPointQueryResult qr;
    cudaGetDriverEntryPoint("cuTensorMapEncodeTiled", &pf, cudaEnableDefault, &qr);
    EncodeFn enc = (EncodeFn)pf;

    CUtensorMap tmX, tmWqkv, tmAtt, tmWout, tmQ, tmK, tmVT;
    make_tm(enc, &tmX,    xr,    1024, MROWS,           32, 128);
    make_tm(enc, &tmWqkv, wqkvr, 1024, 3072,            32, 256);
    make_tm(enc, &tmAtt,  att,   1024, MROWS,           32, 128);
    make_tm(enc, &tmWout, woutr, 1024, 1024,            32, 256);
    make_tm(enc, &tmQ,    qp,    64,   (uint64_t)BB * HH * TT, 32, 256);
    make_tm(enc, &tmK,    kp,    64,   (uint64_t)BB * HH * TT, 32, 64);
    make_tm(enc, &tmVT,   vtp,   2048, (uint64_t)BB * HH * DD, 32, 64);

    cudaFuncSetAttribute(gemm_tma<0>, cudaFuncAttributeMaxDynamicSharedMemorySize, GEMM_SMEM_BYTES);
    cudaFuncSetAttribute(gemm_tma<1>, cudaFuncAttributeMaxDynamicSharedMemorySize, GEMM_SMEM_BYTES);
    cudaFuncSetAttribute(flash_attn_tma, cudaFuncAttributeMaxDynamicSharedMemorySize, FA_SMEM_BYTES);

    // 0) round operands to tf32 once
    {
        int n4 = MROWS * EE / 4;
        round_tf32<<<(n4 + 255) / 256, 256>>>((const float4*)x, (float4*)xr, n4);
        n4 = 3 * EE * EE / 4;
        round_tf32<<<(n4 + 255) / 256, 256>>>((const float4*)Wqkv, (float4*)wqkvr, n4);
        n4 = EE * EE / 4;
        round_tf32<<<(n4 + 255) / 256, 256>>>((const float4*)Wout, (float4*)woutr, n4);
    }

    // 1) QKV projection + scatter (q scaled, v transposed)
    {
        dim3 grid(3 * EE / 256, MROWS / 128);   // (12, 64)
        gemm_tma<1><<<grid, 256, GEMM_SMEM_BYTES>>>(tmX, tmWqkv, nullptr);
    }

    // 2) Causal flash attention -> g_att
    {
        dim3 grid(TT / 256, BB * HH);           // (8, 64)
        flash_attn_tma<<<grid, 256, FA_SMEM_BYTES>>>(tmQ, tmK, tmVT);
    }

    // 3) Output projection
    {
        dim3 grid(EE / 256, MROWS / 128);       // (4, 64)
        gemm_tma<0><<<grid, 256, GEMM_SMEM_BYTES>>>(tmAtt, tmWout, out);
    }
}

// round 6
// speedup vs baseline: 5.0335x; 1.0919x over previous
#include <cuda_runtime.h>
#include <cuda.h>
#include <math.h>
#include <stdint.h>

#define BB 4
#define TT 2048
#define EE 1024
#define HH 16
#define DD 64
#define MROWS (BB * TT)   // 8192

// ---------------------------------------------------------------------------
// Scratch (__device__ globals; allocation-free rule)
// ---------------------------------------------------------------------------
__device__ float g_xr[(size_t)MROWS * EE];       // x rounded to tf32
__device__ float g_wqkvr[(size_t)3 * EE * EE];   // W_qkv rounded
__device__ float g_woutr[(size_t)EE * EE];       // W_out rounded
__device__ float g_q[(size_t)BB * HH * TT * DD]; // scaled+rounded Q [bh][t][d]
__device__ float g_k[(size_t)BB * HH * TT * DD]; // rounded K [bh][t][d]
__device__ float g_vt[(size_t)BB * HH * DD * TT];// rounded V^T [bh][d][t]
__device__ float g_att[(size_t)MROWS * EE];      // attention out, rounded

// ---------------------------------------------------------------------------
// Helpers (base-PTX for sm_103: mma.sync, ldmatrix, TMA bulk tensor, mbarrier)
// ---------------------------------------------------------------------------
__device__ __forceinline__ uint32_t f2tf(float f) {
    uint32_t u;
    asm("cvt.rna.tf32.f32 %0, %1;" : "=r"(u) : "f"(f));
    return u;
}

__device__ __forceinline__ float ex2f(float x) {
    float y;
    asm("ex2.approx.f32 %0, %1;" : "=f"(y) : "f"(x));
    return y;
}

__device__ __forceinline__ void mma_tf32(float c[4],
                                         uint32_t a0, uint32_t a1, uint32_t a2, uint32_t a3,
                                         uint32_t b0, uint32_t b1) {
    asm volatile(
        "mma.sync.aligned.m16n8k8.row.col.f32.tf32.tf32.f32 "
        "{%0,%1,%2,%3}, {%4,%5,%6,%7}, {%8,%9}, {%0,%1,%2,%3};\n"
        : "+f"(c[0]), "+f"(c[1]), "+f"(c[2]), "+f"(c[3])
        : "r"(a0), "r"(a1), "r"(a2), "r"(a3), "r"(b0), "r"(b1));
}

__device__ __forceinline__ void ldsm_x4(uint32_t& d0, uint32_t& d1, uint32_t& d2, uint32_t& d3,
                                        uint32_t addr) {
    asm volatile("ldmatrix.sync.aligned.m8n8.x4.shared.b16 {%0,%1,%2,%3}, [%4];"
                 : "=r"(d0), "=r"(d1), "=r"(d2), "=r"(d3) : "r"(addr));
}

__device__ __forceinline__ uint32_t smem_u32(const void* p) {
    uint32_t a;
    asm("{ .reg .u64 t; cvta.to.shared.u64 t, %1; cvt.u32.u64 %0, t; }"
        : "=r"(a) : "l"(p));
    return a;
}

#define MBARRIER_INIT(addr, cnt) \
    asm volatile("mbarrier.init.shared.b64 [%0], %1;" :: "r"((uint32_t)(addr)), "r"((uint32_t)(cnt)) : "memory")

#define MBARRIER_ARRIVE(addr) \
    asm volatile("mbarrier.arrive.shared.b64 _, [%0];" :: "r"((uint32_t)(addr)) : "memory")

#define MBARRIER_EXPECT_TX(addr, bytes) \
    asm volatile("mbarrier.arrive.expect_tx.shared.b64 _, [%0], %1;" :: "r"((uint32_t)(addr)), "r"((uint32_t)(bytes)) : "memory")

#define MBARRIER_WAIT_PARITY(addr, parity) do {                                   \
    uint32_t _mb = (uint32_t)(addr);                                              \
    uint32_t _ph = (uint32_t)(parity);                                            \
    uint32_t _done;                                                               \
    asm volatile("{\n\t.reg .pred p;\n\t"                                         \
        "mbarrier.try_wait.parity.acquire.cta.shared::cta.b64 p, [%1], %2;\n\t"   \
        "selp.b32 %0, 1, 0, p;\n\t}"                                              \
        : "=r"(_done) : "r"(_mb), "r"(_ph) : "memory");                           \
    if (!_done) {                                                                 \
        asm volatile("{\n\t.reg .pred P1;\n\t"                                    \
            "WAIT_LOOP_%=:\n\t"                                                   \
            "mbarrier.try_wait.parity.acquire.cta.shared::cta.b64 P1, [%0], %1, 0x989680;\n\t" \
            "@P1 bra.uni WAIT_DONE_%=;\n\t"                                       \
            "bra.uni WAIT_LOOP_%=;\n\t"                                           \
            "WAIT_DONE_%=:\n\t}"                                                  \
            :: "r"(_mb), "r"(_ph) : "memory");                                    \
    }                                                                             \
} while (0)

#define TMA_LOAD_2D(smem_addr, map_ptr, cx, cy, mbar) \
    asm volatile("cp.async.bulk.tensor.2d.shared::cta.global.tile.mbarrier::complete_tx::bytes " \
                 "[%0], [%1, {%2, %3}], [%4];" \
                 :: "r"((uint32_t)(smem_addr)), "l"(map_ptr), \
                    "r"((int32_t)(cx)), "r"((int32_t)(cy)), "r"((uint32_t)(mbar)) : "memory")

// Q pre-scale: D^-0.5 * log2(e) -> softmax runs in log2 domain (ex2)
#define QSCALE 0.18033688011112042f

// ---------------------------------------------------------------------------
// Prep: round f32 -> tf32 bits (stored as f32)
// ---------------------------------------------------------------------------
__global__ void round_tf32(const float4* __restrict__ src, float4* __restrict__ dst, int n4)
{
    int i = blockIdx.x * blockDim.x + threadIdx.x;
    if (i >= n4) return;
    float4 v = src[i];
    dst[i] = make_float4(__uint_as_float(f2tf(v.x)), __uint_as_float(f2tf(v.y)),
                         __uint_as_float(f2tf(v.z)), __uint_as_float(f2tf(v.w)));
}

// ---------------------------------------------------------------------------
// tf32 GEMM (NT): C[M,N] = A[M,K] * W[N,K]^T, K=1024.
// CTA 128x256, BK=32, 8 warps (2m x 4n), warp tile 64x64.
// TMA (SW128) 3-stage pipeline with full/empty mbarriers; NO block syncs in
// the mainloop (warps drift; empty arrive-count = 8 warps).
// MODE 0: plain row-major store. MODE 1: QKV scatter (q scaled, v transposed).
// ---------------------------------------------------------------------------
#define G_NCH 32
#define G_STAGE_BYTES 49152           // A 128x128B + B 256x128B
#define GEMM_SMEM_BYTES (1024 + 3 * G_STAGE_BYTES)

template <int MODE>
__global__ __launch_bounds__(256, 1)
void gemm_tma(const __grid_constant__ CUtensorMap tmA,
              const __grid_constant__ CUtensorMap tmB,
              float* __restrict__ C)
{
    extern __shared__ char smraw[];
    uint32_t sb = smem_u32(smraw);
    sb = (sb + 1023u) & ~1023u;

    const int tid = threadIdx.x, lane = tid & 31, wid = tid >> 5;
    const int wm = wid & 1, wn = wid >> 1;
    const int g = lane >> 2, t = lane & 3;
    const int m0 = blockIdx.y * 128;
    const int n0 = blockIdx.x * 256;

    const uint32_t mbf = sb;             // full barriers  @ +0,8,16
    const uint32_t mbe = sb + 24;        // empty barriers @ +24,32,40
    const uint32_t st0 = sb + 1024;

    if (tid == 0) {
#pragma unroll
        for (int s = 0; s < 3; ++s) {
            MBARRIER_INIT(mbf + s * 8, 1);
            MBARRIER_INIT(mbe + s * 8, 8);
        }
    }
    __syncthreads();

    auto produce = [&](int c) {
        const int s = c % 3;
        MBARRIER_EXPECT_TX(mbf + s * 8, G_STAGE_BYTES);
        const uint32_t sa = st0 + s * G_STAGE_BYTES;
        TMA_LOAD_2D(sa,         &tmA, c * 32, m0, mbf + s * 8);
        TMA_LOAD_2D(sa + 16384, &tmB, c * 32, n0, mbf + s * 8);
    };

    if (tid == 0) { produce(0); produce(1); produce(2); }

    float acc[4][8][4];
#pragma unroll
    for (int mt = 0; mt < 4; ++mt)
#pragma unroll
        for (int nt = 0; nt < 8; ++nt)
#pragma unroll
            for (int j = 0; j < 4; ++j) acc[mt][nt][j] = 0.f;

    for (int c = 0; c < G_NCH; ++c) {
        MBARRIER_WAIT_PARITY(mbf + (c % 3) * 8, (c / 3) & 1);

        const uint32_t sa = st0 + (c % 3) * G_STAGE_BYTES;
        const uint32_t sw = sa + 16384;

        uint32_t af[2][4][4], bf[2][8][2];
        auto ldfrag = [&](int ks, int p) {
            const int kc2 = ks * 2;                    // 16B-chunk base
#pragma unroll
            for (int mt = 0; mt < 4; ++mt) {
                const int r = wm * 64 + mt * 16 + (lane & 7) + ((lane >> 3) & 1) * 8;
                const int cc = kc2 + (lane >> 4);
                ldsm_x4(af[p][mt][0], af[p][mt][1], af[p][mt][2], af[p][mt][3],
                        sa + r * 128 + ((cc ^ (r & 7)) << 4));
            }
#pragma unroll
            for (int j = 0; j < 4; ++j) {
                const int r = wn * 64 + (j * 2 + ((lane >> 4) & 1)) * 8 + (lane & 7);
                const int cc = kc2 + ((lane >> 3) & 1);
                uint32_t d0, d1, d2, d3;
                ldsm_x4(d0, d1, d2, d3, sw + r * 128 + ((cc ^ (r & 7)) << 4));
                bf[p][2 * j][0] = d0; bf[p][2 * j][1] = d1;
                bf[p][2 * j + 1][0] = d2; bf[p][2 * j + 1][1] = d3;
            }
        };

        ldfrag(0, 0);
#pragma unroll
        for (int ks = 0; ks < 4; ++ks) {
            if (ks < 3) {
                ldfrag(ks + 1, (ks + 1) & 1);
                if (ks == 2 && lane == 0)              // all SMEM reads done
                    MBARRIER_ARRIVE(mbe + (c % 3) * 8);
            }
            const int p = ks & 1;
#pragma unroll
            for (int mt = 0; mt < 4; ++mt)
#pragma unroll
                for (int nt = 0; nt < 8; ++nt)
                    mma_tf32(acc[mt][nt], af[p][mt][0], af[p][mt][1], af[p][mt][2], af[p][mt][3],
                             bf[p][nt][0], bf[p][nt][1]);
        }

        if (tid == 0 && c + 3 < G_NCH) {
            MBARRIER_WAIT_PARITY(mbe + (c % 3) * 8, (c / 3) & 1);
            produce(c + 3);
        }
    }

    // Epilogue
#pragma unroll
    for (int mt = 0; mt < 4; ++mt) {
#pragma unroll
        for (int nt = 0; nt < 8; ++nt) {
            const int r0 = m0 + wm * 64 + mt * 16 + g;
            const int col = n0 + wn * 64 + nt * 8 + 2 * t;
            if (MODE == 0) {
                *(float2*)(C + (size_t)r0 * EE + col) =
                    make_float2(acc[mt][nt][0], acc[mt][nt][1]);
                *(float2*)(C + (size_t)(r0 + 8) * EE + col) =
                    make_float2(acc[mt][nt][2], acc[mt][nt][3]);
            } else {
                const int which = col >> 10;
                const int rem = col & 1023;
                const int h = rem >> 6;
                const int d = rem & 63;
#pragma unroll
                for (int half = 0; half < 2; ++half) {
                    const int row = r0 + half * 8;
                    const float v0 = acc[mt][nt][2 * half];
                    const float v1 = acc[mt][nt][2 * half + 1];
                    const int bh = (row >> 11) * HH + h;
                    const int tt = row & 2047;
                    if (which == 0) {
                        *(float2*)(g_q + ((size_t)bh * TT + tt) * DD + d) =
                            make_float2(__uint_as_float(f2tf(v0 * QSCALE)),
                                        __uint_as_float(f2tf(v1 * QSCALE)));
                    } else if (which == 1) {
                        *(float2*)(g_k + ((size_t)bh * TT + tt) * DD + d) =
                            make_float2(__uint_as_float(f2tf(v0)),
                                        __uint_as_float(f2tf(v1)));
                    } else {
                        g_vt[((size_t)bh * DD + d) * TT + tt]     = __uint_as_float(f2tf(v0));
                        g_vt[((size_t)bh * DD + d + 1) * TT + tt] = __uint_as_float(f2tf(v1));
                    }
                }
            }
        }
    }
}

// ---------------------------------------------------------------------------
// Causal flash attention: q-tile 256, kv-tile 64, 8 warps (warp owns 32 rows).
// TMA-staged Q/K/V^T (SW128), ldmatrix, 3-stage kv pipeline with full/empty
// mbarriers, no block syncs in the mainloop. Softmax in log2 domain (ex2).
// SMEM (from aligned base):
//   0      : barriers (q_full @0, kv_full @8..31, kv_empty @32..55)
//   1024   : Q   (2 x 32KB regions, by d-half)
//   66560  : P   (2 x 32KB regions, by key-half)
//   132096 : K stages  (3 x 16KB; each 2 x 8KB regions by d-half)
//   181248 : VT stages (3 x 16KB; each 2 x 8KB regions by key-half)
// ---------------------------------------------------------------------------
#define FA_Q_OFF   1024
#define FA_P_OFF   (FA_Q_OFF + 65536)
#define FA_K_OFF   (FA_P_OFF + 65536)
#define FA_VT_OFF  (FA_K_OFF + 3 * 16384)
#define FA_SMEM_BYTES (FA_VT_OFF + 3 * 16384 + 1024)

__global__ __launch_bounds__(256, 1)
void flash_attn_tma(const __grid_constant__ CUtensorMap tmQ,
                    const __grid_constant__ CUtensorMap tmK,
                    const __grid_constant__ CUtensorMap tmVT)
{
    extern __shared__ char smraw[];
    uint32_t sb = smem_u32(smraw);
    sb = (sb + 1023u) & ~1023u;

    const int qt = gridDim.x - 1 - blockIdx.x;   // long tiles first
    const int bh = blockIdx.y;
    const int q0 = qt * 256;

    const int tid = threadIdx.x, lane = tid & 31, wid = tid >> 5;
    const int g = lane >> 2, t = lane & 3;
    const int wrow = wid * 32;

    const uint32_t qb  = sb + FA_Q_OFF;
    const uint32_t pb  = sb + FA_P_OFF;
    const uint32_t kb  = sb + FA_K_OFF;
    const uint32_t vtb = sb + FA_VT_OFF;
    const uint32_t mbf = sb + 8;    // kv full @ 8,16,24
    const uint32_t mbe = sb + 32;   // kv empty @ 32,40,48

    if (tid == 0) {
        MBARRIER_INIT(sb + 0, 1);
#pragma unroll
        for (int s = 0; s < 3; ++s) {
            MBARRIER_INIT(mbf + s * 8, 1);
            MBARRIER_INIT(mbe + s * 8, 8);
        }
    }
    __syncthreads();

    auto produce_kv = [&](int kt) {
        const int s = kt % 3;
        const int k0 = kt * 64;
        MBARRIER_EXPECT_TX(mbf + s * 8, 32768);
#pragma unroll
        for (int h = 0; h < 2; ++h) {
            TMA_LOAD_2D(kb + s * 16384 + h * 8192, &tmK,
                        h * 32, bh * TT + k0, mbf + s * 8);
            TMA_LOAD_2D(vtb + s * 16384 + h * 8192, &tmVT,
                        k0 + h * 32, bh * 64, mbf + s * 8);
        }
    };

    const int ktmax = 4 * qt + 3;
    if (tid == 0) {
        MBARRIER_EXPECT_TX(sb + 0, 65536);
        TMA_LOAD_2D(qb,         &tmQ, 0,  bh * TT + q0, sb + 0);
        TMA_LOAD_2D(qb + 32768, &tmQ, 32, bh * TT + q0, sb + 0);
        produce_kv(0);
        produce_kv(1);
        produce_kv(2);
    }
    MBARRIER_WAIT_PARITY(sb + 0, 0);

    float o[2][8][4];
#pragma unroll
    for (int mt = 0; mt < 2; ++mt)
#pragma unroll
        for (int nt = 0; nt < 8; ++nt)
#pragma unroll
            for (int j = 0; j < 4; ++j) o[mt][nt][j] = 0.f;
    float mr[2][2] = {{-INFINITY, -INFINITY}, {-INFINITY, -INFINITY}};
    float lr[2][2] = {{0.f, 0.f}, {0.f, 0.f}};

    for (int kt = 0; kt <= ktmax; ++kt) {
        const int s3 = kt % 3;
        const int ph = (kt / 3) & 1;
        MBARRIER_WAIT_PARITY(mbf + s3 * 8, ph);

        const int k0 = kt * 64;
        const bool active = (k0 <= q0 + wrow + 31);

        if (active) {
            const uint32_t ks_b = kb + s3 * 16384;
            const uint32_t vt_b = vtb + s3 * 16384;

            // --- S = Q K^T (scale & log2e pre-folded into Q) ---
            float s[2][8][4];
#pragma unroll
            for (int mt = 0; mt < 2; ++mt)
#pragma unroll
                for (int nt = 0; nt < 8; ++nt)
#pragma unroll
                    for (int j = 0; j < 4; ++j) s[mt][nt][j] = 0.f;

#pragma unroll
            for (int ks = 0; ks < 8; ++ks) {
                const int kc2 = ks * 2;
                uint32_t a[2][4];
#pragma unroll
                for (int mt = 0; mt < 2; ++mt) {
                    const int r = wrow + mt * 16 + (lane & 7) + ((lane >> 3) & 1) * 8;
                    const int cc = kc2 + (lane >> 4);
                    ldsm_x4(a[mt][0], a[mt][1], a[mt][2], a[mt][3],
                            qb + (cc >> 3) * 32768 + r * 128 + ((((cc & 7)) ^ (r & 7)) << 4));
                }
                uint32_t b[8][2];
#pragma unroll
                for (int j = 0; j < 4; ++j) {
                    const int r = (j * 2 + ((lane >> 4) & 1)) * 8 + (lane & 7);
                    const int cc = kc2 + ((lane >> 3) & 1);
                    uint32_t d0, d1, d2, d3;
                    ldsm_x4(d0, d1, d2, d3,
                            ks_b + (cc >> 3) * 8192 + r * 128 + ((((cc & 7)) ^ (r & 7)) << 4));
                    b[2 * j][0] = d0; b[2 * j][1] = d1;
                    b[2 * j + 1][0] = d2; b[2 * j + 1][1] = d3;
                }
#pragma unroll
                for (int mt = 0; mt < 2; ++mt)
#pragma unroll
                    for (int nt = 0; nt < 8; ++nt)
                        mma_tf32(s[mt][nt], a[mt][0], a[mt][1], a[mt][2], a[mt][3],
                                 b[nt][0], b[nt][1]);
            }

            // --- causal mask (diagonal region only) ---
            if (k0 + 63 > q0 + wrow) {
#pragma unroll
                for (int mt = 0; mt < 2; ++mt) {
                    const int rlo = q0 + wrow + mt * 16 + g;
#pragma unroll
                    for (int nt = 0; nt < 8; ++nt) {
                        const int key = k0 + nt * 8 + 2 * t;
                        if (key > rlo)         s[mt][nt][0] = -INFINITY;
                        if (key + 1 > rlo)     s[mt][nt][1] = -INFINITY;
                        if (key > rlo + 8)     s[mt][nt][2] = -INFINITY;
                        if (key + 1 > rlo + 8) s[mt][nt][3] = -INFINITY;
                    }
                }
            }

            // --- online softmax (log2 domain) + P store ---
#pragma unroll
            for (int mt = 0; mt < 2; ++mt) {
                float mx0 = -INFINITY, mx1 = -INFINITY;
#pragma unroll
                for (int nt = 0; nt < 8; ++nt) {
                    mx0 = fmaxf(mx0, fmaxf(s[mt][nt][0], s[mt][nt][1]));
                    mx1 = fmaxf(mx1, fmaxf(s[mt][nt][2], s[mt][nt][3]));
                }
                mx0 = fmaxf(mx0, __shfl_xor_sync(0xffffffffu, mx0, 1));
                mx0 = fmaxf(mx0, __shfl_xor_sync(0xffffffffu, mx0, 2));
                mx1 = fmaxf(mx1, __shfl_xor_sync(0xffffffffu, mx1, 1));
                mx1 = fmaxf(mx1, __shfl_xor_sync(0xffffffffu, mx1, 2));

                const float mn0 = fmaxf(mr[mt][0], mx0);
                const float mn1 = fmaxf(mr[mt][1], mx1);
                const float al0 = ex2f(mr[mt][0] - mn0);
                const float al1 = ex2f(mr[mt][1] - mn1);
                mr[mt][0] = mn0; mr[mt][1] = mn1;

                float s0 = 0.f, s1 = 0.f;
#pragma unroll
                for (int nt = 0; nt < 8; ++nt) {
                    s[mt][nt][0] = ex2f(s[mt][nt][0] - mn0);
                    s[mt][nt][1] = ex2f(s[mt][nt][1] - mn0);
                    s[mt][nt][2] = ex2f(s[mt][nt][2] - mn1);
                    s[mt][nt][3] = ex2f(s[mt][nt][3] - mn1);
                    s0 += s[mt][nt][0] + s[mt][nt][1];
                    s1 += s[mt][nt][2] + s[mt][nt][3];
                }
                s0 += __shfl_xor_sync(0xffffffffu, s0, 1);
                s0 += __shfl_xor_sync(0xffffffffu, s0, 2);
                s1 += __shfl_xor_sync(0xffffffffu, s1, 1);
                s1 += __shfl_xor_sync(0xffffffffu, s1, 2);

                lr[mt][0] = lr[mt][0] * al0 + s0;
                lr[mt][1] = lr[mt][1] * al1 + s1;
#pragma unroll
                for (int nt = 0; nt < 8; ++nt) {
                    o[mt][nt][0] *= al0; o[mt][nt][1] *= al0;
                    o[mt][nt][2] *= al1; o[mt][nt][3] *= al1;
                }

#pragma unroll
                for (int half = 0; half < 2; ++half) {
                    const int pr = wrow + mt * 16 + g + half * 8;
#pragma unroll
                    for (int nt = 0; nt < 8; ++nt) {
                        const int w = nt * 8 + 2 * t;
                        const int cc = w >> 2;
                        const uint32_t addr = pb + (cc >> 3) * 32768 + pr * 128 +
                                              (((cc & 7) ^ (pr & 7)) << 4) + (w & 3) * 4;
                        const uint2 val = make_uint2(f2tf(s[mt][nt][2 * half]),
                                                     f2tf(s[mt][nt][2 * half + 1]));
                        asm volatile("st.shared.v2.b32 [%0], {%1, %2};"
                                     :: "r"(addr), "r"(val.x), "r"(val.y) : "memory");
                    }
                }
            }
            __syncwarp();

            // --- O += P V ---
#pragma unroll
            for (int ks = 0; ks < 8; ++ks) {
                const int kc2 = ks * 2;
                uint32_t a[2][4];
#pragma unroll
                for (int mt = 0; mt < 2; ++mt) {
                    const int r = wrow + mt * 16 + (lane & 7) + ((lane >> 3) & 1) * 8;
                    const int cc = kc2 + (lane >> 4);
                    ldsm_x4(a[mt][0], a[mt][1], a[mt][2], a[mt][3],
                            pb + (cc >> 3) * 32768 + r * 128 + ((((cc & 7)) ^ (r & 7)) << 4));
                }
                uint32_t b[8][2];
#pragma unroll
                for (int j = 0; j < 4; ++j) {
                    const int r = (j * 2 + ((lane >> 4) & 1)) * 8 + (lane & 7);
                    const int cc = kc2 + ((lane >> 3) & 1);
                    uint32_t d0, d1, d2, d3;
                    ldsm_x4(d0, d1, d2, d3,
                            vt_b + (cc >> 3) * 8192 + r * 128 + ((((cc & 7)) ^ (r & 7)) << 4));
                    b[2 * j][0] = d0; b[2 * j][1] = d1;
                    b[2 * j + 1][0] = d2; b[2 * j + 1][1] = d3;
                }
#pragma unroll
                for (int mt = 0; mt < 2; ++mt)
#pragma unroll
                    for (int nt = 0; nt < 8; ++nt)
                        mma_tf32(o[mt][nt], a[mt][0], a[mt][1], a[mt][2], a[mt][3],
                                 b[nt][0], b[nt][1]);
            }
        }

        if (lane == 0) MBARRIER_ARRIVE(mbe + s3 * 8);

        if (tid == 0 && kt + 3 <= ktmax) {
            MBARRIER_WAIT_PARITY(mbe + s3 * 8, ph);
            produce_kv(kt + 3);
        }
    }

    // --- epilogue: normalize, round to tf32, write g_att [B,T,E] ---
    const int b = bh >> 4, h = bh & 15;
#pragma unroll
    for (int mt = 0; mt < 2; ++mt) {
#pragma unroll
        for (int half = 0; half < 2; ++half) {
            const int row = q0 + wrow + mt * 16 + g + half * 8;
            const float inv = 1.0f / lr[mt][half];
#pragma unroll
            for (int nt = 0; nt < 8; ++nt) {
                const int col = h * 64 + nt * 8 + 2 * t;
                const float v0 = o[mt][nt][2 * half] * inv;
                const float v1 = o[mt][nt][2 * half + 1] * inv;
                *(float2*)&g_att[((size_t)b * TT + row) * EE + col] =
                    make_float2(__uint_as_float(f2tf(v0)), __uint_as_float(f2tf(v1)));
            }
        }
    }
}

// ---------------------------------------------------------------------------
// Host
// ---------------------------------------------------------------------------
typedef CUresult (*EncodeFn)(CUtensorMap*, CUtensorMapDataType, cuuint32_t, void*,
                             const cuuint64_t*, const cuuint64_t*, const cuuint32_t*,
                             const cuuint32_t*, CUtensorMapInterleave, CUtensorMapSwizzle,
                             CUtensorMapL2promotion, CUtensorMapFloatOOBfill);

static void make_tm(EncodeFn enc, CUtensorMap* tm, void* ptr,
                    uint64_t d0, uint64_t d1, uint32_t b0, uint32_t b1)
{
    cuuint64_t dims[2]    = {d0, d1};
    cuuint64_t strides[1] = {d0 * 4};
    cuuint32_t box[2]     = {b0, b1};
    cuuint32_t estr[2]    = {1, 1};
    enc(tm, CU_TENSOR_MAP_DATA_TYPE_FLOAT32, 2, ptr, dims, strides, box, estr,
        CU_TENSOR_MAP_INTERLEAVE_NONE, CU_TENSOR_MAP_SWIZZLE_128B,
        CU_TENSOR_MAP_L2_PROMOTION_L2_128B, CU_TENSOR_MAP_FLOAT_OOB_FILL_NONE);
}

extern "C" void kernel_launch(void* const* d_in, const int* in_sizes, int n_in,
                              void* d_out, int out_size)
{
    const float* x    = (const float*)d_in[0];   // [B,T,E]
    const float* Wqkv = (const float*)d_in[1];   // [3E,E]
    const float* Wout = (const float*)d_in[2];   // [E,E]
    float* out = (float*)d_out;                  // [B,T,E]

    void *xr, *wqkvr, *woutr, *att, *qp, *kp, *vtp;
    cudaGetSymbolAddress(&xr, g_xr);
    cudaGetSymbolAddress(&wqkvr, g_wqkvr);
    cudaGetSymbolAddress(&woutr, g_woutr);
    cudaGetSymbolAddress(&att, g_att);
    cudaGetSymbolAddress(&qp, g_q);
    cudaGetSymbolAddress(&kp, g_k);
    cudaGetSymbolAddress(&vtp, g_vt);

    void* pf = nullptr;
    cudaDriverEntryPointQueryResult qr;
    cudaGetDriverEntryPoint("cuTensorMapEncodeTiled", &pf, cudaEnableDefault, &qr);
    EncodeFn enc = (EncodeFn)pf;

    CUtensorMap tmX, tmWqkv, tmAtt, tmWout, tmQ, tmK, tmVT;
    make_tm(enc, &tmX,    xr,    1024, MROWS,           32, 128);
    make_tm(enc, &tmWqkv, wqkvr, 1024, 3072,            32, 256);
    make_tm(enc, &tmAtt,  att,   1024, MROWS,           32, 128);
    make_tm(enc, &tmWout, woutr, 1024, 1024,            32, 256);
    make_tm(enc, &tmQ,    qp,    64,   (uint64_t)BB * HH * TT, 32, 256);
    make_tm(enc, &tmK,    kp,    64,   (uint64_t)BB * HH * TT, 32, 64);
    make_tm(enc, &tmVT,   vtp,   2048, (uint64_t)BB * HH * DD, 32, 64);

    cudaFuncSetAttribute(gemm_tma<0>, cudaFuncAttributeMaxDynamicSharedMemorySize, GEMM_SMEM_BYTES);
    cudaFuncSetAttribute(gemm_tma<1>, cudaFuncAttributeMaxDynamicSharedMemorySize, GEMM_SMEM_BYTES);
    cudaFuncSetAttribute(flash_attn_tma, cudaFuncAttributeMaxDynamicSharedMemorySize, FA_SMEM_BYTES);

    // 0) round operands to tf32 once
    {
        int n4 = MROWS * EE / 4;
        round_tf32<<<(n4 + 255) / 256, 256>>>((const float4*)x, (float4*)xr, n4);
        n4 = 3 * EE * EE / 4;
        round_tf32<<<(n4 + 255) / 256, 256>>>((const float4*)Wqkv, (float4*)wqkvr, n4);
        n4 = EE * EE / 4;
        round_tf32<<<(n4 + 255) / 256, 256>>>((const float4*)Wout, (float4*)woutr, n4);
    }

    // 1) QKV projection + scatter (q scaled, v transposed)
    {
        dim3 grid(3 * EE / 256, MROWS / 128);   // (12, 64)
        gemm_tma<1><<<grid, 256, GEMM_SMEM_BYTES>>>(tmX, tmWqkv, nullptr);
    }

    // 2) Causal flash attention -> g_att
    {
        dim3 grid(TT / 256, BB * HH);           // (8, 64)
        flash_attn_tma<<<grid, 256, FA_SMEM_BYTES>>>(tmQ, tmK, tmVT);
    }

    // 3) Output projection
    {
        dim3 grid(EE / 256, MROWS / 128);       // (4, 64)
        gemm_tma<0><<<grid, 256, GEMM_SMEM_BYTES>>>(tmAtt, tmWout, out);
    }
}

// round 7
// speedup vs baseline: 8.6559x; 1.7197x over previous
#include <cuda_runtime.h>
#include <cuda.h>
#include <cuda_fp16.h>
#include <math.h>
#include <stdint.h>

#define BB 4
#define TT 2048
#define EE 1024
#define HH 16
#define DD 64
#define MROWS (BB * TT)   // 8192

// ---------------------------------------------------------------------------
// Scratch (__device__ globals; allocation-free rule) — all fp16 operands
// ---------------------------------------------------------------------------
__device__ __half g_xh[(size_t)MROWS * EE];
__device__ __half g_wqkvh[(size_t)3 * EE * EE];
__device__ __half g_wouth[(size_t)EE * EE];
__device__ __half g_qh[(size_t)BB * HH * TT * DD];  // scaled Q [bh][t][d]
__device__ __half g_kh[(size_t)BB * HH * TT * DD];  // K [bh][t][d]
__device__ __half g_vth[(size_t)BB * HH * DD * TT]; // V^T [bh][d][t]
__device__ __half g_atth[(size_t)MROWS * EE];       // attention out

// ---------------------------------------------------------------------------
// Helpers (base-PTX: mma.sync f16, ldmatrix, TMA bulk tensor, mbarrier)
// ---------------------------------------------------------------------------
__device__ __forceinline__ float ex2f(float x) {
    float y;
    asm("ex2.approx.f32 %0, %1;" : "=f"(y) : "f"(x));
    return y;
}

__device__ __forceinline__ uint32_t f2h2(float lo, float hi) {
    __half2 h = __floats2half2_rn(lo, hi);
    return *(uint32_t*)&h;
}

__device__ __forceinline__ void mma_f16(float c[4],
                                        uint32_t a0, uint32_t a1, uint32_t a2, uint32_t a3,
                                        uint32_t b0, uint32_t b1) {
    asm volatile(
        "mma.sync.aligned.m16n8k16.row.col.f32.f16.f16.f32 "
        "{%0,%1,%2,%3}, {%4,%5,%6,%7}, {%8,%9}, {%0,%1,%2,%3};\n"
        : "+f"(c[0]), "+f"(c[1]), "+f"(c[2]), "+f"(c[3])
        : "r"(a0), "r"(a1), "r"(a2), "r"(a3), "r"(b0), "r"(b1));
}

__device__ __forceinline__ void ldsm_x4(uint32_t& d0, uint32_t& d1, uint32_t& d2, uint32_t& d3,
                                        uint32_t addr) {
    asm volatile("ldmatrix.sync.aligned.m8n8.x4.shared.b16 {%0,%1,%2,%3}, [%4];"
                 : "=r"(d0), "=r"(d1), "=r"(d2), "=r"(d3) : "r"(addr));
}

__device__ __forceinline__ uint32_t smem_u32(const void* p) {
    uint32_t a;
    asm("{ .reg .u64 t; cvta.to.shared.u64 t, %1; cvt.u32.u64 %0, t; }"
        : "=r"(a) : "l"(p));
    return a;
}

#define MBARRIER_INIT(addr, cnt) \
    asm volatile("mbarrier.init.shared.b64 [%0], %1;" :: "r"((uint32_t)(addr)), "r"((uint32_t)(cnt)) : "memory")

#define MBARRIER_ARRIVE(addr) \
    asm volatile("mbarrier.arrive.shared.b64 _, [%0];" :: "r"((uint32_t)(addr)) : "memory")

#define MBARRIER_EXPECT_TX(addr, bytes) \
    asm volatile("mbarrier.arrive.expect_tx.shared.b64 _, [%0], %1;" :: "r"((uint32_t)(addr)), "r"((uint32_t)(bytes)) : "memory")

#define MBARRIER_WAIT_PARITY(addr, parity) do {                                   \
    uint32_t _mb = (uint32_t)(addr);                                              \
    uint32_t _ph = (uint32_t)(parity);                                            \
    uint32_t _done;                                                               \
    asm volatile("{\n\t.reg .pred p;\n\t"                                         \
        "mbarrier.try_wait.parity.acquire.cta.shared::cta.b64 p, [%1], %2;\n\t"   \
        "selp.b32 %0, 1, 0, p;\n\t}"                                              \
        : "=r"(_done) : "r"(_mb), "r"(_ph) : "memory");                           \
    if (!_done) {                                                                 \
        asm volatile("{\n\t.reg .pred P1;\n\t"                                    \
            "WAIT_LOOP_%=:\n\t"                                                   \
            "mbarrier.try_wait.parity.acquire.cta.shared::cta.b64 P1, [%0], %1, 0x989680;\n\t" \
            "@P1 bra.uni WAIT_DONE_%=;\n\t"                                       \
            "bra.uni WAIT_LOOP_%=;\n\t"                                           \
            "WAIT_DONE_%=:\n\t}"                                                  \
            :: "r"(_mb), "r"(_ph) : "memory");                                    \
    }                                                                             \
} while (0)

#define TMA_LOAD_2D(smem_addr, map_ptr, cx, cy, mbar) \
    asm volatile("cp.async.bulk.tensor.2d.shared::cta.global.tile.mbarrier::complete_tx::bytes " \
                 "[%0], [%1, {%2, %3}], [%4];" \
                 :: "r"((uint32_t)(smem_addr)), "l"(map_ptr), \
                    "r"((int32_t)(cx)), "r"((int32_t)(cy)), "r"((uint32_t)(mbar)) : "memory")

// Q pre-scale: D^-0.5 * log2(e) -> softmax in log2 domain (ex2)
#define QSCALE 0.18033688011112042f

// ---------------------------------------------------------------------------
// Prep: f32 -> fp16
// ---------------------------------------------------------------------------
__global__ void conv_half(const float4* __restrict__ src, uint2* __restrict__ dst, int n4)
{
    int i = blockIdx.x * blockDim.x + threadIdx.x;
    if (i >= n4) return;
    float4 v = src[i];
    dst[i] = make_uint2(f2h2(v.x, v.y), f2h2(v.z, v.w));
}

// ---------------------------------------------------------------------------
// fp16 GEMM (NT): C[M,N] = A[M,K] * W[N,K]^T, K=1024, fp32 accum.
// CTA 128x256, BK=64 (one 128B SW128 row), 16 chunks, 8 warps (2m x 4n),
// warp tile 64x64, m16n8k16. TMA 3-stage full/empty mbarrier pipeline,
// no block syncs in mainloop.
// MODE 0: fp32 row-major store. MODE 1: QKV scatter (q scaled, v transposed).
// ---------------------------------------------------------------------------
#define G_NCH 16
#define G_STAGE_BYTES 49152           // A 128x128B + B 256x128B
#define GEMM_SMEM_BYTES (1024 + 3 * G_STAGE_BYTES)

template <int MODE>
__global__ __launch_bounds__(256, 1)
void gemm_tma(const __grid_constant__ CUtensorMap tmA,
              const __grid_constant__ CUtensorMap tmB,
              float* __restrict__ C)
{
    extern __shared__ char smraw[];
    uint32_t sb = smem_u32(smraw);
    sb = (sb + 1023u) & ~1023u;

    const int tid = threadIdx.x, lane = tid & 31, wid = tid >> 5;
    const int wm = wid & 1, wn = wid >> 1;
    const int g = lane >> 2, t = lane & 3;
    const int m0 = blockIdx.y * 128;
    const int n0 = blockIdx.x * 256;

    const uint32_t mbf = sb;             // full barriers  @ +0,8,16
    const uint32_t mbe = sb + 24;        // empty barriers @ +24,32,40
    const uint32_t st0 = sb + 1024;

    if (tid == 0) {
#pragma unroll
        for (int s = 0; s < 3; ++s) {
            MBARRIER_INIT(mbf + s * 8, 1);
            MBARRIER_INIT(mbe + s * 8, 8);
        }
    }
    __syncthreads();

    auto produce = [&](int c) {
        const int s = c % 3;
        MBARRIER_EXPECT_TX(mbf + s * 8, G_STAGE_BYTES);
        const uint32_t sa = st0 + s * G_STAGE_BYTES;
        TMA_LOAD_2D(sa,         &tmA, c * 64, m0, mbf + s * 8);
        TMA_LOAD_2D(sa + 16384, &tmB, c * 64, n0, mbf + s * 8);
    };

    if (tid == 0) { produce(0); produce(1); produce(2); }

    float acc[4][8][4];
#pragma unroll
    for (int mt = 0; mt < 4; ++mt)
#pragma unroll
        for (int nt = 0; nt < 8; ++nt)
#pragma unroll
            for (int j = 0; j < 4; ++j) acc[mt][nt][j] = 0.f;

    for (int c = 0; c < G_NCH; ++c) {
        MBARRIER_WAIT_PARITY(mbf + (c % 3) * 8, (c / 3) & 1);

        const uint32_t sa = st0 + (c % 3) * G_STAGE_BYTES;
        const uint32_t sw = sa + 16384;

        uint32_t af[2][4][4], bf[2][8][2];
        auto ldfrag = [&](int ks, int p) {
            const int kc2 = ks * 2;                    // 16B-chunk base (8 fp16)
#pragma unroll
            for (int mt = 0; mt < 4; ++mt) {
                const int r = wm * 64 + mt * 16 + (lane & 7) + ((lane >> 3) & 1) * 8;
                const int cc = kc2 + (lane >> 4);
                ldsm_x4(af[p][mt][0], af[p][mt][1], af[p][mt][2], af[p][mt][3],
                        sa + r * 128 + ((cc ^ (r & 7)) << 4));
            }
#pragma unroll
            for (int j = 0; j < 4; ++j) {
                const int r = wn * 64 + (j * 2 + ((lane >> 4) & 1)) * 8 + (lane & 7);
                const int cc = kc2 + ((lane >> 3) & 1);
                uint32_t d0, d1, d2, d3;
                ldsm_x4(d0, d1, d2, d3, sw + r * 128 + ((cc ^ (r & 7)) << 4));
                bf[p][2 * j][0] = d0; bf[p][2 * j][1] = d1;
                bf[p][2 * j + 1][0] = d2; bf[p][2 * j + 1][1] = d3;
            }
        };

        ldfrag(0, 0);
#pragma unroll
        for (int ks = 0; ks < 4; ++ks) {               // BK=64 / k16
            if (ks < 3) {
                ldfrag(ks + 1, (ks + 1) & 1);
                if (ks == 2 && lane == 0)
                    MBARRIER_ARRIVE(mbe + (c % 3) * 8);
            }
            const int p = ks & 1;
#pragma unroll
            for (int mt = 0; mt < 4; ++mt)
#pragma unroll
                for (int nt = 0; nt < 8; ++nt)
                    mma_f16(acc[mt][nt], af[p][mt][0], af[p][mt][1], af[p][mt][2], af[p][mt][3],
                            bf[p][nt][0], bf[p][nt][1]);
        }

        if (tid == 0 && c + 3 < G_NCH) {
            MBARRIER_WAIT_PARITY(mbe + (c % 3) * 8, (c / 3) & 1);
            produce(c + 3);
        }
    }

    // Epilogue
#pragma unroll
    for (int mt = 0; mt < 4; ++mt) {
#pragma unroll
        for (int nt = 0; nt < 8; ++nt) {
            const int r0 = m0 + wm * 64 + mt * 16 + g;
            const int col = n0 + wn * 64 + nt * 8 + 2 * t;
            if (MODE == 0) {
                *(float2*)(C + (size_t)r0 * EE + col) =
                    make_float2(acc[mt][nt][0], acc[mt][nt][1]);
                *(float2*)(C + (size_t)(r0 + 8) * EE + col) =
                    make_float2(acc[mt][nt][2], acc[mt][nt][3]);
            } else {
                const int which = col >> 10;
                const int rem = col & 1023;
                const int h = rem >> 6;
                const int d = rem & 63;
#pragma unroll
                for (int half = 0; half < 2; ++half) {
                    const int row = r0 + half * 8;
                    const float v0 = acc[mt][nt][2 * half];
                    const float v1 = acc[mt][nt][2 * half + 1];
                    const int bh = (row >> 11) * HH + h;
                    const int tt = row & 2047;
                    if (which == 0) {
                        *(uint32_t*)(g_qh + ((size_t)bh * TT + tt) * DD + d) =
                            f2h2(v0 * QSCALE, v1 * QSCALE);
                    } else if (which == 1) {
                        *(uint32_t*)(g_kh + ((size_t)bh * TT + tt) * DD + d) =
                            f2h2(v0, v1);
                    } else {
                        g_vth[((size_t)bh * DD + d) * TT + tt]     = __float2half(v0);
                        g_vth[((size_t)bh * DD + d + 1) * TT + tt] = __float2half(v1);
                    }
                }
            }
        }
    }
}

// ---------------------------------------------------------------------------
// Causal flash attention (fp16 mma, fp32 accum): q-tile 256, kv-tile 64,
// 8 warps (warp owns 32 rows). TMA SW128, 3-stage kv full/empty pipeline,
// no block syncs in mainloop. Softmax in log2 domain (ex2).
// SMEM (from aligned base), all tiles have 128B rows:
//   0      : barriers (q_full @0, kv_full @8..31, kv_empty @32..55)
//   1024   : Q   (256 x 128B = 32KB)
//   33792  : P   (256 x 128B = 32KB)
//   66560  : K stages  (3 x 8KB)
//   91136  : VT stages (3 x 8KB)
// ---------------------------------------------------------------------------
#define FA_Q_OFF   1024
#define FA_P_OFF   (FA_Q_OFF + 32768)
#define FA_K_OFF   (FA_P_OFF + 32768)
#define FA_VT_OFF  (FA_K_OFF + 3 * 8192)
#define FA_SMEM_BYTES (FA_VT_OFF + 3 * 8192 + 1024)

__global__ __launch_bounds__(256, 1)
void flash_attn_tma(const __grid_constant__ CUtensorMap tmQ,
                    const __grid_constant__ CUtensorMap tmK,
                    const __grid_constant__ CUtensorMap tmVT)
{
    extern __shared__ char smraw[];
    uint32_t sb = smem_u32(smraw);
    sb = (sb + 1023u) & ~1023u;

    const int qt = gridDim.x - 1 - blockIdx.x;   // long tiles first
    const int bh = blockIdx.y;
    const int q0 = qt * 256;

    const int tid = threadIdx.x, lane = tid & 31, wid = tid >> 5;
    const int g = lane >> 2, t = lane & 3;
    const int wrow = wid * 32;

    const uint32_t qb  = sb + FA_Q_OFF;
    const uint32_t pb  = sb + FA_P_OFF;
    const uint32_t kb  = sb + FA_K_OFF;
    const uint32_t vtb = sb + FA_VT_OFF;
    const uint32_t mbf = sb + 8;    // kv full @ 8,16,24
    const uint32_t mbe = sb + 32;   // kv empty @ 32,40,48

    if (tid == 0) {
        MBARRIER_INIT(sb + 0, 1);
#pragma unroll
        for (int s = 0; s < 3; ++s) {
            MBARRIER_INIT(mbf + s * 8, 1);
            MBARRIER_INIT(mbe + s * 8, 8);
        }
    }
    __syncthreads();

    auto produce_kv = [&](int kt) {
        const int s = kt % 3;
        const int k0 = kt * 64;
        MBARRIER_EXPECT_TX(mbf + s * 8, 16384);
        TMA_LOAD_2D(kb + s * 8192,  &tmK,  0,  bh * TT + k0, mbf + s * 8);
        TMA_LOAD_2D(vtb + s * 8192, &tmVT, k0, bh * 64,      mbf + s * 8);
    };

    const int ktmax = 4 * qt + 3;
    if (tid == 0) {
        MBARRIER_EXPECT_TX(sb + 0, 32768);
        TMA_LOAD_2D(qb, &tmQ, 0, bh * TT + q0, sb + 0);
        produce_kv(0);
        produce_kv(1);
        produce_kv(2);
    }
    MBARRIER_WAIT_PARITY(sb + 0, 0);

    float o[2][8][4];
#pragma unroll
    for (int mt = 0; mt < 2; ++mt)
#pragma unroll
        for (int nt = 0; nt < 8; ++nt)
#pragma unroll
            for (int j = 0; j < 4; ++j) o[mt][nt][j] = 0.f;
    float mr[2][2] = {{-INFINITY, -INFINITY}, {-INFINITY, -INFINITY}};
    float lr[2][2] = {{0.f, 0.f}, {0.f, 0.f}};

    for (int kt = 0; kt <= ktmax; ++kt) {
        const int s3 = kt % 3;
        const int ph = (kt / 3) & 1;
        MBARRIER_WAIT_PARITY(mbf + s3 * 8, ph);

        const int k0 = kt * 64;
        const bool active = (k0 <= q0 + wrow + 31);

        if (active) {
            const uint32_t ks_b = kb + s3 * 8192;
            const uint32_t vt_b = vtb + s3 * 8192;

            // --- S = Q K^T (scale & log2e folded into Q) ---
            float s[2][8][4];
#pragma unroll
            for (int mt = 0; mt < 2; ++mt)
#pragma unroll
                for (int nt = 0; nt < 8; ++nt)
#pragma unroll
                    for (int j = 0; j < 4; ++j) s[mt][nt][j] = 0.f;

#pragma unroll
            for (int ks = 0; ks < 4; ++ks) {           // d = 64 / k16
                const int kc2 = ks * 2;
                uint32_t a[2][4];
#pragma unroll
                for (int mt = 0; mt < 2; ++mt) {
                    const int r = wrow + mt * 16 + (lane & 7) + ((lane >> 3) & 1) * 8;
                    const int cc = kc2 + (lane >> 4);
                    ldsm_x4(a[mt][0], a[mt][1], a[mt][2], a[mt][3],
                            qb + r * 128 + ((cc ^ (r & 7)) << 4));
                }
                uint32_t b[8][2];
#pragma unroll
                for (int j = 0; j < 4; ++j) {
                    const int r = (j * 2 + ((lane >> 4) & 1)) * 8 + (lane & 7);
                    const int cc = kc2 + ((lane >> 3) & 1);
                    uint32_t d0, d1, d2, d3;
                    ldsm_x4(d0, d1, d2, d3, ks_b + r * 128 + ((cc ^ (r & 7)) << 4));
                    b[2 * j][0] = d0; b[2 * j][1] = d1;
                    b[2 * j + 1][0] = d2; b[2 * j + 1][1] = d3;
                }
#pragma unroll
                for (int mt = 0; mt < 2; ++mt)
#pragma unroll
                    for (int nt = 0; nt < 8; ++nt)
                        mma_f16(s[mt][nt], a[mt][0], a[mt][1], a[mt][2], a[mt][3],
                                b[nt][0], b[nt][1]);
            }

            // --- causal mask (diagonal region only) ---
            if (k0 + 63 > q0 + wrow) {
#pragma unroll
                for (int mt = 0; mt < 2; ++mt) {
                    const int rlo = q0 + wrow + mt * 16 + g;
#pragma unroll
                    for (int nt = 0; nt < 8; ++nt) {
                        const int key = k0 + nt * 8 + 2 * t;
                        if (key > rlo)         s[mt][nt][0] = -INFINITY;
                        if (key + 1 > rlo)     s[mt][nt][1] = -INFINITY;
                        if (key > rlo + 8)     s[mt][nt][2] = -INFINITY;
                        if (key + 1 > rlo + 8) s[mt][nt][3] = -INFINITY;
                    }
                }
            }

            // --- online softmax (log2 domain) + P store (fp16, swizzled) ---
#pragma unroll
            for (int mt = 0; mt < 2; ++mt) {
                float mx0 = -INFINITY, mx1 = -INFINITY;
#pragma unroll
                for (int nt = 0; nt < 8; ++nt) {
                    mx0 = fmaxf(mx0, fmaxf(s[mt][nt][0], s[mt][nt][1]));
                    mx1 = fmaxf(mx1, fmaxf(s[mt][nt][2], s[mt][nt][3]));
                }
                mx0 = fmaxf(mx0, __shfl_xor_sync(0xffffffffu, mx0, 1));
                mx0 = fmaxf(mx0, __shfl_xor_sync(0xffffffffu, mx0, 2));
                mx1 = fmaxf(mx1, __shfl_xor_sync(0xffffffffu, mx1, 1));
                mx1 = fmaxf(mx1, __shfl_xor_sync(0xffffffffu, mx1, 2));

                const float mn0 = fmaxf(mr[mt][0], mx0);
                const float mn1 = fmaxf(mr[mt][1], mx1);
                const float al0 = ex2f(mr[mt][0] - mn0);
                const float al1 = ex2f(mr[mt][1] - mn1);
                mr[mt][0] = mn0; mr[mt][1] = mn1;

                float s0 = 0.f, s1 = 0.f;
#pragma unroll
                for (int nt = 0; nt < 8; ++nt) {
                    s[mt][nt][0] = ex2f(s[mt][nt][0] - mn0);
                    s[mt][nt][1] = ex2f(s[mt][nt][1] - mn0);
                    s[mt][nt][2] = ex2f(s[mt][nt][2] - mn1);
                    s[mt][nt][3] = ex2f(s[mt][nt][3] - mn1);
                    s0 += s[mt][nt][0] + s[mt][nt][1];
                    s1 += s[mt][nt][2] + s[mt][nt][3];
                }
                s0 += __shfl_xor_sync(0xffffffffu, s0, 1);
                s0 += __shfl_xor_sync(0xffffffffu, s0, 2);
                s1 += __shfl_xor_sync(0xffffffffu, s1, 1);
                s1 += __shfl_xor_sync(0xffffffffu, s1, 2);

                lr[mt][0] = lr[mt][0] * al0 + s0;
                lr[mt][1] = lr[mt][1] * al1 + s1;
#pragma unroll
                for (int nt = 0; nt < 8; ++nt) {
                    o[mt][nt][0] *= al0; o[mt][nt][1] *= al0;
                    o[mt][nt][2] *= al1; o[mt][nt][3] *= al1;
                }

#pragma unroll
                for (int half = 0; half < 2; ++half) {
                    const int pr = wrow + mt * 16 + g + half * 8;
#pragma unroll
                    for (int nt = 0; nt < 8; ++nt) {
                        // key w = nt*8 + 2t -> byte 2w: chunk = nt, offset 4t
                        const uint32_t addr = pb + pr * 128 +
                                              (((nt) ^ (pr & 7)) << 4) + 4 * t;
                        const uint32_t val = f2h2(s[mt][nt][2 * half],
                                                  s[mt][nt][2 * half + 1]);
                        asm volatile("st.shared.b32 [%0], %1;"
                                     :: "r"(addr), "r"(val) : "memory");
                    }
                }
            }
            __syncwarp();

            // --- O += P V ---
#pragma unroll
            for (int ks = 0; ks < 4; ++ks) {           // keys = 64 / k16
                const int kc2 = ks * 2;
                uint32_t a[2][4];
#pragma unroll
                for (int mt = 0; mt < 2; ++mt) {
                    const int r = wrow + mt * 16 + (lane & 7) + ((lane >> 3) & 1) * 8;
                    const int cc = kc2 + (lane >> 4);
                    ldsm_x4(a[mt][0], a[mt][1], a[mt][2], a[mt][3],
                            pb + r * 128 + ((cc ^ (r & 7)) << 4));
                }
                uint32_t b[8][2];
#pragma unroll
                for (int j = 0; j < 4; ++j) {
                    const int r = (j * 2 + ((lane >> 4) & 1)) * 8 + (lane & 7);
                    const int cc = kc2 + ((lane >> 3) & 1);
                    uint32_t d0, d1, d2, d3;
                    ldsm_x4(d0, d1, d2, d3, vt_b + r * 128 + ((cc ^ (r & 7)) << 4));
                    b[2 * j][0] = d0; b[2 * j][1] = d1;
                    b[2 * j + 1][0] = d2; b[2 * j + 1][1] = d3;
                }
#pragma unroll
                for (int mt = 0; mt < 2; ++mt)
#pragma unroll
                    for (int nt = 0; nt < 8; ++nt)
                        mma_f16(o[mt][nt], a[mt][0], a[mt][1], a[mt][2], a[mt][3],
                                b[nt][0], b[nt][1]);
            }
        }

        if (lane == 0) MBARRIER_ARRIVE(mbe + s3 * 8);

        if (tid == 0 && kt + 3 <= ktmax) {
            MBARRIER_WAIT_PARITY(mbe + s3 * 8, ph);
            produce_kv(kt + 3);
        }
    }

    // --- epilogue: normalize, write fp16 att [B,T,E] ---
    const int b = bh >> 4, h = bh & 15;
#pragma unroll
    for (int mt = 0; mt < 2; ++mt) {
#pragma unroll
        for (int half = 0; half < 2; ++half) {
            const int row = q0 + wrow + mt * 16 + g + half * 8;
            const float inv = 1.0f / lr[mt][half];
#pragma unroll
            for (int nt = 0; nt < 8; ++nt) {
                const int col = h * 64 + nt * 8 + 2 * t;
                *(uint32_t*)(g_atth + ((size_t)b * TT + row) * EE + col) =
                    f2h2(o[mt][nt][2 * half] * inv, o[mt][nt][2 * half + 1] * inv);
            }
        }
    }
}

// ---------------------------------------------------------------------------
// Host
// ---------------------------------------------------------------------------
typedef CUresult (*EncodeFn)(CUtensorMap*, CUtensorMapDataType, cuuint32_t, void*,
                             const cuuint64_t*, const cuuint64_t*, const cuuint32_t*,
                             const cuuint32_t*, CUtensorMapInterleave, CUtensorMapSwizzle,
                             CUtensorMapL2promotion, CUtensorMapFloatOOBfill);

static void make_tm(EncodeFn enc, CUtensorMap* tm, void* ptr,
                    uint64_t d0, uint64_t d1, uint32_t b0, uint32_t b1)
{
    cuuint64_t dims[2]    = {d0, d1};
    cuuint64_t strides[1] = {d0 * 2};
    cuuint32_t box[2]     = {b0, b1};
    cuuint32_t estr[2]    = {1, 1};
    enc(tm, CU_TENSOR_MAP_DATA_TYPE_FLOAT16, 2, ptr, dims, strides, box, estr,
        CU_TENSOR_MAP_INTERLEAVE_NONE, CU_TENSOR_MAP_SWIZZLE_128B,
        CU_TENSOR_MAP_L2_PROMOTION_L2_128B, CU_TENSOR_MAP_FLOAT_OOB_FILL_NONE);
}

extern "C" void kernel_launch(void* const* d_in, const int* in_sizes, int n_in,
                              void* d_out, int out_size)
{
    const float* x    = (const float*)d_in[0];   // [B,T,E]
    const float* Wqkv = (const float*)d_in[1];   // [3E,E]
    const float* Wout = (const float*)d_in[2];   // [E,E]
    float* out = (float*)d_out;                  // [B,T,E]

    void *xh, *wqkvh, *wouth, *atth, *qp, *kp, *vtp;
    cudaGetSymbolAddress(&xh, g_xh);
    cudaGetSymbolAddress(&wqkvh, g_wqkvh);
    cudaGetSymbolAddress(&wouth, g_wouth);
    cudaGetSymbolAddress(&atth, g_atth);
    cudaGetSymbolAddress(&qp, g_qh);
    cudaGetSymbolAddress(&kp, g_kh);
    cudaGetSymbolAddress(&vtp, g_vth);

    void* pf = nullptr;
    cudaDriverEntryPointQueryResult qr;
    cudaGetDriverEntryPoint("cuTensorMapEncodeTiled", &pf, cudaEnableDefault, &qr);
    EncodeFn enc = (EncodeFn)pf;

    CUtensorMap tmX, tmWqkv, tmAtt, tmWout, tmQ, tmK, tmVT;
    make_tm(enc, &tmX,    xh,    1024, MROWS,               64, 128);
    make_tm(enc, &tmWqkv, wqkvh, 1024, 3072,                64, 256);
    make_tm(enc, &tmAtt,  atth,  1024, MROWS,               64, 128);
    make_tm(enc, &tmWout, wouth, 1024, 1024,                64, 256);
    make_tm(enc, &tmQ,    qp,    64,   (uint64_t)BB * HH * TT, 64, 256);
    make_tm(enc, &tmK,    kp,    64,   (uint64_t)BB * HH * TT, 64, 64);
    make_tm(enc, &tmVT,   vtp,   2048, (uint64_t)BB * HH * DD, 64, 64);

    cudaFuncSetAttribute(gemm_tma<0>, cudaFuncAttributeMaxDynamicSharedMemorySize, GEMM_SMEM_BYTES);
    cudaFuncSetAttribute(gemm_tma<1>, cudaFuncAttributeMaxDynamicSharedMemorySize, GEMM_SMEM_BYTES);
    cudaFuncSetAttribute(flash_attn_tma, cudaFuncAttributeMaxDynamicSharedMemorySize, FA_SMEM_BYTES);

    // 0) convert operands to fp16
    {
        int n4 = MROWS * EE / 4;
        conv_half<<<(n4 + 255) / 256, 256>>>((const float4*)x, (uint2*)xh, n4);
        n4 = 3 * EE * EE / 4;
        conv_half<<<(n4 + 255) / 256, 256>>>((const float4*)Wqkv, (uint2*)wqkvh, n4);
        n4 = EE * EE / 4;
        conv_half<<<(n4 + 255) / 256, 256>>>((const float4*)Wout, (uint2*)wouth, n4);
    }

    // 1) QKV projection + scatter (q scaled, v transposed)
    {
        dim3 grid(3 * EE / 256, MROWS / 128);   // (12, 64)
        gemm_tma<1><<<grid, 256, GEMM_SMEM_BYTES>>>(tmX, tmWqkv, nullptr);
    }

    // 2) Causal flash attention -> g_atth (fp16)
    {
        dim3 grid(TT / 256, BB * HH);           // (8, 64)
        flash_attn_tma<<<grid, 256, FA_SMEM_BYTES>>>(tmQ, tmK, tmVT);
    }

    // 3) Output projection (fp32 out)
    {
        dim3 grid(EE / 256, MROWS / 128);       // (4, 64)
        gemm_tma<0><<<grid, 256, GEMM_SMEM_BYTES>>>(tmAtt, tmWout, out);
    }
}

// round 8
// speedup vs baseline: 9.0965x; 1.0509x over previous
#include <cuda_runtime.h>
#include <cuda.h>
#include <cuda_fp16.h>
#include <math.h>
#include <stdint.h>

#define BB 4
#define TT 2048
#define EE 1024
#define HH 16
#define DD 64
#define MROWS (BB * TT)   // 8192

// ---------------------------------------------------------------------------
// Scratch (__device__ globals; allocation-free rule) — fp16 operands
// ---------------------------------------------------------------------------
__device__ __half g_xh[(size_t)MROWS * EE];
__device__ __half g_wqkvh[(size_t)3 * EE * EE];
__device__ __half g_wouth[(size_t)EE * EE];
__device__ __half g_qh[(size_t)BB * HH * TT * DD];  // scaled Q [bh][t][d]
__device__ __half g_kh[(size_t)BB * HH * TT * DD];  // K [bh][t][d]
__device__ __half g_vth[(size_t)BB * HH * DD * TT]; // V^T [bh][d][t]
__device__ __half g_atth[(size_t)MROWS * EE];       // attention out

// ---------------------------------------------------------------------------
// Helpers
// ---------------------------------------------------------------------------
__device__ __forceinline__ float ex2f(float x) {
    float y;
    asm("ex2.approx.f32 %0, %1;" : "=f"(y) : "f"(x));
    return y;
}

__device__ __forceinline__ uint32_t f2h2(float lo, float hi) {
    __half2 h = __floats2half2_rn(lo, hi);
    return *(uint32_t*)&h;
}

__device__ __forceinline__ void mma_f16(float c[4],
                                        uint32_t a0, uint32_t a1, uint32_t a2, uint32_t a3,
                                        uint32_t b0, uint32_t b1) {
    asm volatile(
        "mma.sync.aligned.m16n8k16.row.col.f32.f16.f16.f32 "
        "{%0,%1,%2,%3}, {%4,%5,%6,%7}, {%8,%9}, {%0,%1,%2,%3};\n"
        : "+f"(c[0]), "+f"(c[1]), "+f"(c[2]), "+f"(c[3])
        : "r"(a0), "r"(a1), "r"(a2), "r"(a3), "r"(b0), "r"(b1));
}

__device__ __forceinline__ void ldsm_x4(uint32_t& d0, uint32_t& d1, uint32_t& d2, uint32_t& d3,
                                        uint32_t addr) {
    asm volatile("ldmatrix.sync.aligned.m8n8.x4.shared.b16 {%0,%1,%2,%3}, [%4];"
                 : "=r"(d0), "=r"(d1), "=r"(d2), "=r"(d3) : "r"(addr));
}

__device__ __forceinline__ uint32_t smem_u32(const void* p) {
    uint32_t a;
    asm("{ .reg .u64 t; cvta.to.shared.u64 t, %1; cvt.u32.u64 %0, t; }"
        : "=r"(a) : "l"(p));
    return a;
}

#define MBARRIER_INIT(addr, cnt) \
    asm volatile("mbarrier.init.shared.b64 [%0], %1;" :: "r"((uint32_t)(addr)), "r"((uint32_t)(cnt)) : "memory")

#define MBARRIER_ARRIVE(addr) \
    asm volatile("mbarrier.arrive.shared.b64 _, [%0];" :: "r"((uint32_t)(addr)) : "memory")

#define MBARRIER_EXPECT_TX(addr, bytes) \
    asm volatile("mbarrier.arrive.expect_tx.shared.b64 _, [%0], %1;" :: "r"((uint32_t)(addr)), "r"((uint32_t)(bytes)) : "memory")

#define MBARRIER_WAIT_PARITY(addr, parity) do {                                   \
    uint32_t _mb = (uint32_t)(addr);                                              \
    uint32_t _ph = (uint32_t)(parity);                                            \
    uint32_t _done;                                                               \
    asm volatile("{\n\t.reg .pred p;\n\t"                                         \
        "mbarrier.try_wait.parity.acquire.cta.shared::cta.b64 p, [%1], %2;\n\t"   \
        "selp.b32 %0, 1, 0, p;\n\t}"                                              \
        : "=r"(_done) : "r"(_mb), "r"(_ph) : "memory");                           \
    if (!_done) {                                                                 \
        asm volatile("{\n\t.reg .pred P1;\n\t"                                    \
            "WAIT_LOOP_%=:\n\t"                                                   \
            "mbarrier.try_wait.parity.acquire.cta.shared::cta.b64 P1, [%0], %1, 0x989680;\n\t" \
            "@P1 bra.uni WAIT_DONE_%=;\n\t"                                       \
            "bra.uni WAIT_LOOP_%=;\n\t"                                           \
            "WAIT_DONE_%=:\n\t}"                                                  \
            :: "r"(_mb), "r"(_ph) : "memory");                                    \
    }                                                                             \
} while (0)

#define TMA_LOAD_2D(smem_addr, map_ptr, cx, cy, mbar) \
    asm volatile("cp.async.bulk.tensor.2d.shared::cta.global.tile.mbarrier::complete_tx::bytes " \
                 "[%0], [%1, {%2, %3}], [%4];" \
                 :: "r"((uint32_t)(smem_addr)), "l"(map_ptr), \
                    "r"((int32_t)(cx)), "r"((int32_t)(cy)), "r"((uint32_t)(mbar)) : "memory")

// Q pre-scale: D^-0.5 * log2(e)
#define QSCALE 0.18033688011112042f

// ---------------------------------------------------------------------------
// Prep: f32 -> fp16
// ---------------------------------------------------------------------------
__global__ void conv_half(const float4* __restrict__ src, uint2* __restrict__ dst, int n4)
{
    int i = blockIdx.x * blockDim.x + threadIdx.x;
    if (i >= n4) return;
    float4 v = src[i];
    dst[i] = make_uint2(f2h2(v.x, v.y), f2h2(v.z, v.w));
}

// ---------------------------------------------------------------------------
// fp16 GEMM (NT): C[M,N] = A[M,K] * W[N,K]^T, K=1024, fp32 accum.
// CTA 128x128, BK=64, 16 chunks, 8 warps (2m x 4n), warp tile 64x32.
// 2-stage TMA full/empty pipeline, no block syncs in mainloop, 2 CTAs/SM.
// MODE 0: fp32 row-major store. MODE 1: QKV scatter (q scaled, v transposed).
// ---------------------------------------------------------------------------
#define G_NCH 16
#define G_STAGE_BYTES 32768           // A 128x128B + B 128x128B
#define GEMM_SMEM_BYTES (1024 + 2 * G_STAGE_BYTES)

template <int MODE>
__global__ __launch_bounds__(256, 2)
void gemm_tma(const __grid_constant__ CUtensorMap tmA,
              const __grid_constant__ CUtensorMap tmB,
              float* __restrict__ C)
{
    extern __shared__ char smraw[];
    uint32_t sb = smem_u32(smraw);
    sb = (sb + 1023u) & ~1023u;

    const int tid = threadIdx.x, lane = tid & 31, wid = tid >> 5;
    const int wm = wid & 1, wn = wid >> 1;
    const int g = lane >> 2, t = lane & 3;
    const int m0 = blockIdx.y * 128;
    const int n0 = blockIdx.x * 128;

    const uint32_t mbf = sb;             // full  @ +0,8
    const uint32_t mbe = sb + 16;        // empty @ +16,24
    const uint32_t st0 = sb + 1024;

    if (tid == 0) {
#pragma unroll
        for (int s = 0; s < 2; ++s) {
            MBARRIER_INIT(mbf + s * 8, 1);
            MBARRIER_INIT(mbe + s * 8, 8);
        }
    }
    __syncthreads();

    auto produce = [&](int c) {
        const int s = c & 1;
        MBARRIER_EXPECT_TX(mbf + s * 8, G_STAGE_BYTES);
        const uint32_t sa = st0 + s * G_STAGE_BYTES;
        TMA_LOAD_2D(sa,         &tmA, c * 64, m0, mbf + s * 8);
        TMA_LOAD_2D(sa + 16384, &tmB, c * 64, n0, mbf + s * 8);
    };

    if (tid == 0) { produce(0); produce(1); }

    float acc[4][4][4];
#pragma unroll
    for (int mt = 0; mt < 4; ++mt)
#pragma unroll
        for (int nt = 0; nt < 4; ++nt)
#pragma unroll
            for (int j = 0; j < 4; ++j) acc[mt][nt][j] = 0.f;

    for (int c = 0; c < G_NCH; ++c) {
        MBARRIER_WAIT_PARITY(mbf + (c & 1) * 8, (c >> 1) & 1);

        const uint32_t sa = st0 + (c & 1) * G_STAGE_BYTES;
        const uint32_t sw = sa + 16384;

        uint32_t af[2][4][4], bf[2][4][2];
        auto ldfrag = [&](int ks, int p) {
            const int kc2 = ks * 2;
#pragma unroll
            for (int mt = 0; mt < 4; ++mt) {
                const int r = wm * 64 + mt * 16 + (lane & 7) + ((lane >> 3) & 1) * 8;
                const int cc = kc2 + (lane >> 4);
                ldsm_x4(af[p][mt][0], af[p][mt][1], af[p][mt][2], af[p][mt][3],
                        sa + r * 128 + ((cc ^ (r & 7)) << 4));
            }
#pragma unroll
            for (int j = 0; j < 2; ++j) {
                const int r = wn * 32 + (j * 2 + ((lane >> 4) & 1)) * 8 + (lane & 7);
                const int cc = kc2 + ((lane >> 3) & 1);
                uint32_t d0, d1, d2, d3;
                ldsm_x4(d0, d1, d2, d3, sw + r * 128 + ((cc ^ (r & 7)) << 4));
                bf[p][2 * j][0] = d0; bf[p][2 * j][1] = d1;
                bf[p][2 * j + 1][0] = d2; bf[p][2 * j + 1][1] = d3;
            }
        };

        ldfrag(0, 0);
#pragma unroll
        for (int ks = 0; ks < 4; ++ks) {
            if (ks < 3) {
                ldfrag(ks + 1, (ks + 1) & 1);
                if (ks == 2 && lane == 0)
                    MBARRIER_ARRIVE(mbe + (c & 1) * 8);
            }
            const int p = ks & 1;
#pragma unroll
            for (int mt = 0; mt < 4; ++mt)
#pragma unroll
                for (int nt = 0; nt < 4; ++nt)
                    mma_f16(acc[mt][nt], af[p][mt][0], af[p][mt][1], af[p][mt][2], af[p][mt][3],
                            bf[p][nt][0], bf[p][nt][1]);
        }

        if (tid == 0 && c + 2 < G_NCH) {
            MBARRIER_WAIT_PARITY(mbe + (c & 1) * 8, (c >> 1) & 1);
            produce(c + 2);
        }
    }

    // Epilogue
#pragma unroll
    for (int mt = 0; mt < 4; ++mt) {
#pragma unroll
        for (int nt = 0; nt < 4; ++nt) {
            const int r0 = m0 + wm * 64 + mt * 16 + g;
            const int col = n0 + wn * 32 + nt * 8 + 2 * t;
            if (MODE == 0) {
                *(float2*)(C + (size_t)r0 * EE + col) =
                    make_float2(acc[mt][nt][0], acc[mt][nt][1]);
                *(float2*)(C + (size_t)(r0 + 8) * EE + col) =
                    make_float2(acc[mt][nt][2], acc[mt][nt][3]);
            } else {
                const int which = col >> 10;
                const int rem = col & 1023;
                const int h = rem >> 6;
                const int d = rem & 63;
#pragma unroll
                for (int half = 0; half < 2; ++half) {
                    const int row = r0 + half * 8;
                    const float v0 = acc[mt][nt][2 * half];
                    const float v1 = acc[mt][nt][2 * half + 1];
                    const int bh = (row >> 11) * HH + h;
                    const int tt = row & 2047;
                    if (which == 0) {
                        *(uint32_t*)(g_qh + ((size_t)bh * TT + tt) * DD + d) =
                            f2h2(v0 * QSCALE, v1 * QSCALE);
                    } else if (which == 1) {
                        *(uint32_t*)(g_kh + ((size_t)bh * TT + tt) * DD + d) =
                            f2h2(v0, v1);
                    } else {
                        g_vth[((size_t)bh * DD + d) * TT + tt]     = __float2half(v0);
                        g_vth[((size_t)bh * DD + d + 1) * TT + tt] = __float2half(v1);
                    }
                }
            }
        }
    }
}

// ---------------------------------------------------------------------------
// Causal flash attention (fp16 mma, fp32 accum): q-tile 128, kv-tile 64,
// 8 warps (warp owns 16 rows). TMA SW128, 2-stage kv pipeline, no block
// syncs in mainloop, 2 CTAs/SM. Softmax in log2 domain (ex2).
// SMEM (from aligned base):
//   0      : barriers (q_full @0, kv_full @8,16, kv_empty @24,32)
//   1024   : Q   (128 x 128B = 16KB)
//   17408  : P   (128 x 128B = 16KB)
//   33792  : K stages  (2 x 8KB)
//   50176  : VT stages (2 x 8KB)
// ---------------------------------------------------------------------------
#define FA_Q_OFF   1024
#define FA_P_OFF   (FA_Q_OFF + 16384)
#define FA_K_OFF   (FA_P_OFF + 16384)
#define FA_VT_OFF  (FA_K_OFF + 2 * 8192)
#define FA_SMEM_BYTES (FA_VT_OFF + 2 * 8192 + 1024)

__global__ __launch_bounds__(256, 2)
void flash_attn_tma(const __grid_constant__ CUtensorMap tmQ,
                    const __grid_constant__ CUtensorMap tmK,
                    const __grid_constant__ CUtensorMap tmVT)
{
    extern __shared__ char smraw[];
    uint32_t sb = smem_u32(smraw);
    sb = (sb + 1023u) & ~1023u;

    const int qt = gridDim.x - 1 - blockIdx.x;   // long tiles first
    const int bh = blockIdx.y;
    const int q0 = qt * 128;

    const int tid = threadIdx.x, lane = tid & 31, wid = tid >> 5;
    const int g = lane >> 2, t = lane & 3;
    const int wrow = wid * 16;

    const uint32_t qb  = sb + FA_Q_OFF;
    const uint32_t pb  = sb + FA_P_OFF;
    const uint32_t kb  = sb + FA_K_OFF;
    const uint32_t vtb = sb + FA_VT_OFF;
    const uint32_t mbf = sb + 8;    // kv full @ 8,16
    const uint32_t mbe = sb + 24;   // kv empty @ 24,32

    if (tid == 0) {
        MBARRIER_INIT(sb + 0, 1);
#pragma unroll
        for (int s = 0; s < 2; ++s) {
            MBARRIER_INIT(mbf + s * 8, 1);
            MBARRIER_INIT(mbe + s * 8, 8);
        }
    }
    __syncthreads();

    auto produce_kv = [&](int kt) {
        const int s = kt & 1;
        const int k0 = kt * 64;
        MBARRIER_EXPECT_TX(mbf + s * 8, 16384);
        TMA_LOAD_2D(kb + s * 8192,  &tmK,  0,  bh * TT + k0, mbf + s * 8);
        TMA_LOAD_2D(vtb + s * 8192, &tmVT, k0, bh * 64,      mbf + s * 8);
    };

    const int ktmax = 2 * qt + 1;
    if (tid == 0) {
        MBARRIER_EXPECT_TX(sb + 0, 16384);
        TMA_LOAD_2D(qb, &tmQ, 0, bh * TT + q0, sb + 0);
        produce_kv(0);
        produce_kv(1);
    }
    MBARRIER_WAIT_PARITY(sb + 0, 0);

    float o[8][4];
#pragma unroll
    for (int nt = 0; nt < 8; ++nt)
#pragma unroll
        for (int j = 0; j < 4; ++j) o[nt][j] = 0.f;
    float mr0 = -INFINITY, mr1 = -INFINITY, lr0 = 0.f, lr1 = 0.f;

    for (int kt = 0; kt <= ktmax; ++kt) {
        const int s2 = kt & 1;
        const int ph = (kt >> 1) & 1;
        MBARRIER_WAIT_PARITY(mbf + s2 * 8, ph);

        const int k0 = kt * 64;
        const bool active = (k0 <= q0 + wrow + 15);

        if (active) {
            const uint32_t ks_b = kb + s2 * 8192;
            const uint32_t vt_b = vtb + s2 * 8192;

            // --- S = Q K^T ---
            float s[8][4];
#pragma unroll
            for (int nt = 0; nt < 8; ++nt)
#pragma unroll
                for (int j = 0; j < 4; ++j) s[nt][j] = 0.f;

#pragma unroll
            for (int ks = 0; ks < 4; ++ks) {
                const int kc2 = ks * 2;
                uint32_t a[4];
                {
                    const int r = wrow + (lane & 7) + ((lane >> 3) & 1) * 8;
                    const int cc = kc2 + (lane >> 4);
                    ldsm_x4(a[0], a[1], a[2], a[3],
                            qb + r * 128 + ((cc ^ (r & 7)) << 4));
                }
                uint32_t b[8][2];
#pragma unroll
                for (int j = 0; j < 4; ++j) {
                    const int r = (j * 2 + ((lane >> 4) & 1)) * 8 + (lane & 7);
                    const int cc = kc2 + ((lane >> 3) & 1);
                    uint32_t d0, d1, d2, d3;
                    ldsm_x4(d0, d1, d2, d3, ks_b + r * 128 + ((cc ^ (r & 7)) << 4));
                    b[2 * j][0] = d0; b[2 * j][1] = d1;
                    b[2 * j + 1][0] = d2; b[2 * j + 1][1] = d3;
                }
#pragma unroll
                for (int nt = 0; nt < 8; ++nt)
                    mma_f16(s[nt], a[0], a[1], a[2], a[3], b[nt][0], b[nt][1]);
            }

            // --- causal mask (diagonal region only) ---
            if (k0 + 63 > q0 + wrow) {
                const int rlo = q0 + wrow + g;
#pragma unroll
                for (int nt = 0; nt < 8; ++nt) {
                    const int key = k0 + nt * 8 + 2 * t;
                    if (key > rlo)         s[nt][0] = -INFINITY;
                    if (key + 1 > rlo)     s[nt][1] = -INFINITY;
                    if (key > rlo + 8)     s[nt][2] = -INFINITY;
                    if (key + 1 > rlo + 8) s[nt][3] = -INFINITY;
                }
            }

            // --- online softmax (log2 domain) + P store (fp16, swizzled) ---
            float mx0 = -INFINITY, mx1 = -INFINITY;
#pragma unroll
            for (int nt = 0; nt < 8; ++nt) {
                mx0 = fmaxf(mx0, fmaxf(s[nt][0], s[nt][1]));
                mx1 = fmaxf(mx1, fmaxf(s[nt][2], s[nt][3]));
            }
            mx0 = fmaxf(mx0, __shfl_xor_sync(0xffffffffu, mx0, 1));
            mx0 = fmaxf(mx0, __shfl_xor_sync(0xffffffffu, mx0, 2));
            mx1 = fmaxf(mx1, __shfl_xor_sync(0xffffffffu, mx1, 1));
            mx1 = fmaxf(mx1, __shfl_xor_sync(0xffffffffu, mx1, 2));

            const float mn0 = fmaxf(mr0, mx0);
            const float mn1 = fmaxf(mr1, mx1);
            const float al0 = ex2f(mr0 - mn0);
            const float al1 = ex2f(mr1 - mn1);
            mr0 = mn0; mr1 = mn1;

            float s0 = 0.f, s1 = 0.f;
#pragma unroll
            for (int nt = 0; nt < 8; ++nt) {
                s[nt][0] = ex2f(s[nt][0] - mn0);
                s[nt][1] = ex2f(s[nt][1] - mn0);
                s[nt][2] = ex2f(s[nt][2] - mn1);
                s[nt][3] = ex2f(s[nt][3] - mn1);
                s0 += s[nt][0] + s[nt][1];
                s1 += s[nt][2] + s[nt][3];
            }
            s0 += __shfl_xor_sync(0xffffffffu, s0, 1);
            s0 += __shfl_xor_sync(0xffffffffu, s0, 2);
            s1 += __shfl_xor_sync(0xffffffffu, s1, 1);
            s1 += __shfl_xor_sync(0xffffffffu, s1, 2);

            lr0 = lr0 * al0 + s0;
            lr1 = lr1 * al1 + s1;
#pragma unroll
            for (int nt = 0; nt < 8; ++nt) {
                o[nt][0] *= al0; o[nt][1] *= al0;
                o[nt][2] *= al1; o[nt][3] *= al1;
            }

#pragma unroll
            for (int half = 0; half < 2; ++half) {
                const int pr = wrow + g + half * 8;
#pragma unroll
                for (int nt = 0; nt < 8; ++nt) {
                    const uint32_t addr = pb + pr * 128 +
                                          ((nt ^ (pr & 7)) << 4) + 4 * t;
                    const uint32_t val = f2h2(s[nt][2 * half], s[nt][2 * half + 1]);
                    asm volatile("st.shared.b32 [%0], %1;"
                                 :: "r"(addr), "r"(val) : "memory");
                }
            }
            __syncwarp();

            // --- O += P V ---
#pragma unroll
            for (int ks = 0; ks < 4; ++ks) {
                const int kc2 = ks * 2;
                uint32_t a[4];
                {
                    const int r = wrow + (lane & 7) + ((lane >> 3) & 1) * 8;
                    const int cc = kc2 + (lane >> 4);
                    ldsm_x4(a[0], a[1], a[2], a[3],
                            pb + r * 128 + ((cc ^ (r & 7)) << 4));
                }
                uint32_t b[8][2];
#pragma unroll
                for (int j = 0; j < 4; ++j) {
                    const int r = (j * 2 + ((lane >> 4) & 1)) * 8 + (lane & 7);
                    const int cc = kc2 + ((lane >> 3) & 1);
                    uint32_t d0, d1, d2, d3;
                    ldsm_x4(d0, d1, d2, d3, vt_b + r * 128 + ((cc ^ (r & 7)) << 4));
                    b[2 * j][0] = d0; b[2 * j][1] = d1;
                    b[2 * j + 1][0] = d2; b[2 * j + 1][1] = d3;
                }
#pragma unroll
                for (int nt = 0; nt < 8; ++nt)
                    mma_f16(o[nt], a[0], a[1], a[2], a[3], b[nt][0], b[nt][1]);
            }
        }

        if (lane == 0) MBARRIER_ARRIVE(mbe + s2 * 8);

        if (tid == 0 && kt + 2 <= ktmax) {
            MBARRIER_WAIT_PARITY(mbe + s2 * 8, ph);
            produce_kv(kt + 2);
        }
    }

    // --- epilogue: normalize, write fp16 att [B,T,E] ---
    const int b = bh >> 4, h = bh & 15;
#pragma unroll
    for (int half = 0; half < 2; ++half) {
        const int row = q0 + wrow + g + half * 8;
        const float inv = 1.0f / (half ? lr1 : lr0);
#pragma unroll
        for (int nt = 0; nt < 8; ++nt) {
            const int col = h * 64 + nt * 8 + 2 * t;
            *(uint32_t*)(g_atth + ((size_t)b * TT + row) * EE + col) =
                f2h2(o[nt][2 * half] * inv, o[nt][2 * half + 1] * inv);
        }
    }
}

// ---------------------------------------------------------------------------
// Host
// ---------------------------------------------------------------------------
typedef CUresult (*EncodeFn)(CUtensorMap*, CUtensorMapDataType, cuuint32_t, void*,
                             const cuuint64_t*, const cuuint64_t*, const cuuint32_t*,
                             const cuuint32_t*, CUtensorMapInterleave, CUtensorMapSwizzle,
                             CUtensorMapL2promotion, CUtensorMapFloatOOBfill);

static void make_tm(EncodeFn enc, CUtensorMap* tm, void* ptr,
                    uint64_t d0, uint64_t d1, uint32_t b0, uint32_t b1)
{
    cuuint64_t dims[2]    = {d0, d1};
    cuuint64_t strides[1] = {d0 * 2};
    cuuint32_t box[2]     = {b0, b1};
    cuuint32_t estr[2]    = {1, 1};
    enc(tm, CU_TENSOR_MAP_DATA_TYPE_FLOAT16, 2, ptr, dims, strides, box, estr,
        CU_TENSOR_MAP_INTERLEAVE_NONE, CU_TENSOR_MAP_SWIZZLE_128B,
        CU_TENSOR_MAP_L2_PROMOTION_L2_128B, CU_TENSOR_MAP_FLOAT_OOB_FILL_NONE);
}

extern "C" void kernel_launch(void* const* d_in, const int* in_sizes, int n_in,
                              void* d_out, int out_size)
{
    const float* x    = (const float*)d_in[0];   // [B,T,E]
    const float* Wqkv = (const float*)d_in[1];   // [3E,E]
    const float* Wout = (const float*)d_in[2];   // [E,E]
    float* out = (float*)d_out;                  // [B,T,E]

    void *xh, *wqkvh, *wouth, *atth, *qp, *kp, *vtp;
    cudaGetSymbolAddress(&xh, g_xh);
    cudaGetSymbolAddress(&wqkvh, g_wqkvh);
    cudaGetSymbolAddress(&wouth, g_wouth);
    cudaGetSymbolAddress(&atth, g_atth);
    cudaGetSymbolAddress(&qp, g_qh);
    cudaGetSymbolAddress(&kp, g_kh);
    cudaGetSymbolAddress(&vtp, g_vth);

    void* pf = nullptr;
    cudaDriverEntryPointQueryResult qr;
    cudaGetDriverEntryPoint("cuTensorMapEncodeTiled", &pf, cudaEnableDefault, &qr);
    EncodeFn enc = (EncodeFn)pf;

    CUtensorMap tmX, tmWqkv, tmAtt, tmWout, tmQ, tmK, tmVT;
    make_tm(enc, &tmX,    xh,    1024, MROWS,               64, 128);
    make_tm(enc, &tmWqkv, wqkvh, 1024, 3072,                64, 128);
    make_tm(enc, &tmAtt,  atth,  1024, MROWS,               64, 128);
    make_tm(enc, &tmWout, wouth, 1024, 1024,                64, 128);
    make_tm(enc, &tmQ,    qp,    64,   (uint64_t)BB * HH * TT, 64, 128);
    make_tm(enc, &tmK,    kp,    64,   (uint64_t)BB * HH * TT, 64, 64);
    make_tm(enc, &tmVT,   vtp,   2048, (uint64_t)BB * HH * DD, 64, 64);

    cudaFuncSetAttribute(gemm_tma<0>, cudaFuncAttributeMaxDynamicSharedMemorySize, GEMM_SMEM_BYTES);
    cudaFuncSetAttribute(gemm_tma<1>, cudaFuncAttributeMaxDynamicSharedMemorySize, GEMM_SMEM_BYTES);
    cudaFuncSetAttribute(flash_attn_tma, cudaFuncAttributeMaxDynamicSharedMemorySize, FA_SMEM_BYTES);

    // 0) convert operands to fp16
    {
        int n4 = MROWS * EE / 4;
        conv_half<<<(n4 + 255) / 256, 256>>>((const float4*)x, (uint2*)xh, n4);
        n4 = 3 * EE * EE / 4;
        conv_half<<<(n4 + 255) / 256, 256>>>((const float4*)Wqkv, (uint2*)wqkvh, n4);
        n4 = EE * EE / 4;
        conv_half<<<(n4 + 255) / 256, 256>>>((const float4*)Wout, (uint2*)wouth, n4);
    }

    // 1) QKV projection + scatter (q scaled, v transposed)
    {
        dim3 grid(3 * EE / 128, MROWS / 128);   // (24, 64)
        gemm_tma<1><<<grid, 256, GEMM_SMEM_BYTES>>>(tmX, tmWqkv, nullptr);
    }

    // 2) Causal flash attention -> g_atth (fp16)
    {
        dim3 grid(TT / 128, BB * HH);           // (16, 64)
        flash_attn_tma<<<grid, 256, FA_SMEM_BYTES>>>(tmQ, tmK, tmVT);
    }

    // 3) Output projection (fp32 out)
    {
        dim3 grid(EE / 128, MROWS / 128);       // (8, 64)
        gemm_tma<0><<<grid, 256, GEMM_SMEM_BYTES>>>(tmAtt, tmWout, out);
    }
}

// round 10
// speedup vs baseline: 9.3816x; 1.0313x over previous
#include <cuda_runtime.h>
#include <cuda.h>
#include <cuda_fp16.h>
#include <math.h>
#include <stdint.h>

#define BB 4
#define TT 2048
#define EE 1024
#define HH 16
#define DD 64
#define MROWS (BB * TT)   // 8192

// ---------------------------------------------------------------------------
// Scratch (__device__ globals; allocation-free rule) — fp16 operands
// ---------------------------------------------------------------------------
__device__ __half g_xh[(size_t)MROWS * EE];
__device__ __half g_wqkvh[(size_t)3 * EE * EE];
__device__ __half g_wouth[(size_t)EE * EE];
__device__ __half g_qh[(size_t)BB * HH * TT * DD];  // scaled Q [bh][t][d]
__device__ __half g_kh[(size_t)BB * HH * TT * DD];  // K [bh][t][d]
__device__ __half g_vth[(size_t)BB * HH * DD * TT]; // V^T [bh][d][t]
__device__ __half g_atth[(size_t)MROWS * EE];       // attention out

// ---------------------------------------------------------------------------
// Helpers
// ---------------------------------------------------------------------------
__device__ __forceinline__ float ex2f(float x) {
    float y;
    asm("ex2.approx.f32 %0, %1;" : "=f"(y) : "f"(x));
    return y;
}

__device__ __forceinline__ uint32_t f2h2(float lo, float hi) {
    __half2 h = __floats2half2_rn(lo, hi);
    return *(uint32_t*)&h;
}

__device__ __forceinline__ void mma_f16(float c[4],
                                        uint32_t a0, uint32_t a1, uint32_t a2, uint32_t a3,
                                        uint32_t b0, uint32_t b1) {
    asm volatile(
        "mma.sync.aligned.m16n8k16.row.col.f32.f16.f16.f32 "
        "{%0,%1,%2,%3}, {%4,%5,%6,%7}, {%8,%9}, {%0,%1,%2,%3};\n"
        : "+f"(c[0]), "+f"(c[1]), "+f"(c[2]), "+f"(c[3])
        : "r"(a0), "r"(a1), "r"(a2), "r"(a3), "r"(b0), "r"(b1));
}

__device__ __forceinline__ void ldsm_x4(uint32_t& d0, uint32_t& d1, uint32_t& d2, uint32_t& d3,
                                        uint32_t addr) {
    asm volatile("ldmatrix.sync.aligned.m8n8.x4.shared.b16 {%0,%1,%2,%3}, [%4];"
                 : "=r"(d0), "=r"(d1), "=r"(d2), "=r"(d3) : "r"(addr));
}

__device__ __forceinline__ uint32_t smem_u32(const void* p) {
    uint32_t a;
    asm("{ .reg .u64 t; cvta.to.shared.u64 t, %1; cvt.u32.u64 %0, t; }"
        : "=r"(a) : "l"(p));
    return a;
}

#define MBARRIER_INIT(addr, cnt) \
    asm volatile("mbarrier.init.shared.b64 [%0], %1;" :: "r"((uint32_t)(addr)), "r"((uint32_t)(cnt)) : "memory")

#define MBARRIER_ARRIVE(addr) \
    asm volatile("mbarrier.arrive.shared.b64 _, [%0];" :: "r"((uint32_t)(addr)) : "memory")

#define MBARRIER_EXPECT_TX(addr, bytes) \
    asm volatile("mbarrier.arrive.expect_tx.shared.b64 _, [%0], %1;" :: "r"((uint32_t)(addr)), "r"((uint32_t)(bytes)) : "memory")

#define MBARRIER_WAIT_PARITY(addr, parity) do {                                   \
    uint32_t _mb = (uint32_t)(addr);                                              \
    uint32_t _ph = (uint32_t)(parity);                                            \
    uint32_t _done;                                                               \
    asm volatile("{\n\t.reg .pred p;\n\t"                                         \
        "mbarrier.try_wait.parity.acquire.cta.shared::cta.b64 p, [%1], %2;\n\t"   \
        "selp.b32 %0, 1, 0, p;\n\t}"                                              \
        : "=r"(_done) : "r"(_mb), "r"(_ph) : "memory");                           \
    if (!_done) {                                                                 \
        asm volatile("{\n\t.reg .pred P1;\n\t"                                    \
            "WAIT_LOOP_%=:\n\t"                                                   \
            "mbarrier.try_wait.parity.acquire.cta.shared::cta.b64 P1, [%0], %1, 0x989680;\n\t" \
            "@P1 bra.uni WAIT_DONE_%=;\n\t"                                       \
            "bra.uni WAIT_LOOP_%=;\n\t"                                           \
            "WAIT_DONE_%=:\n\t}"                                                  \
            :: "r"(_mb), "r"(_ph) : "memory");                                    \
    }                                                                             \
} while (0)

#define TMA_LOAD_2D(smem_addr, map_ptr, cx, cy, mbar) \
    asm volatile("cp.async.bulk.tensor.2d.shared::cta.global.tile.mbarrier::complete_tx::bytes " \
                 "[%0], [%1, {%2, %3}], [%4];" \
                 :: "r"((uint32_t)(smem_addr)), "l"(map_ptr), \
                    "r"((int32_t)(cx)), "r"((int32_t)(cy)), "r"((uint32_t)(mbar)) : "memory")

// Q pre-scale: D^-0.5 * log2(e)
#define QSCALE 0.18033688011112042f

// ---------------------------------------------------------------------------
// Prep: f32 -> fp16
// ---------------------------------------------------------------------------
__global__ void conv_half(const float4* __restrict__ src, uint2* __restrict__ dst, int n4)
{
    int i = blockIdx.x * blockDim.x + threadIdx.x;
    if (i >= n4) return;
    float4 v = src[i];
    dst[i] = make_uint2(f2h2(v.x, v.y), f2h2(v.z, v.w));
}

// ---------------------------------------------------------------------------
// fp16 GEMM (NT): C[M,N] = A[M,K] * W[N,K]^T, K=1024, fp32 accum.
// CTA 128x128, BK=64, 16 chunks, 8 warps (2m x 4n), warp tile 64x32.
// 3-stage TMA full/empty pipeline, no block syncs in mainloop, 2 CTAs/SM.
// MODE 0: fp32 row-major store. MODE 1: QKV scatter (q scaled, v transposed).
// ---------------------------------------------------------------------------
#define G_NCH 16
#define G_STAGE_BYTES 32768           // A 128x128B + B 128x128B
#define GEMM_SMEM_BYTES (1024 + 3 * G_STAGE_BYTES)

template <int MODE>
__global__ __launch_bounds__(256, 2)
void gemm_tma(const __grid_constant__ CUtensorMap tmA,
              const __grid_constant__ CUtensorMap tmB,
              float* __restrict__ C)
{
    extern __shared__ char smraw[];
    uint32_t sb = smem_u32(smraw);
    sb = (sb + 1023u) & ~1023u;

    const int tid = threadIdx.x, lane = tid & 31, wid = tid >> 5;
    const int wm = wid & 1, wn = wid >> 1;
    const int g = lane >> 2, t = lane & 3;
    const int m0 = blockIdx.y * 128;
    const int n0 = blockIdx.x * 128;

    const uint32_t mbf = sb;             // full  @ +0,8,16
    const uint32_t mbe = sb + 24;        // empty @ +24,32,40
    const uint32_t st0 = sb + 1024;

    if (tid == 0) {
#pragma unroll
        for (int s = 0; s < 3; ++s) {
            MBARRIER_INIT(mbf + s * 8, 1);
            MBARRIER_INIT(mbe + s * 8, 8);
        }
    }
    __syncthreads();

    auto produce = [&](int c) {
        const int s = c % 3;
        MBARRIER_EXPECT_TX(mbf + s * 8, G_STAGE_BYTES);
        const uint32_t sa = st0 + s * G_STAGE_BYTES;
        TMA_LOAD_2D(sa,         &tmA, c * 64, m0, mbf + s * 8);
        TMA_LOAD_2D(sa + 16384, &tmB, c * 64, n0, mbf + s * 8);
    };

    if (tid == 0) { produce(0); produce(1); produce(2); }

    float acc[4][4][4];
#pragma unroll
    for (int mt = 0; mt < 4; ++mt)
#pragma unroll
        for (int nt = 0; nt < 4; ++nt)
#pragma unroll
            for (int j = 0; j < 4; ++j) acc[mt][nt][j] = 0.f;

    for (int c = 0; c < G_NCH; ++c) {
        MBARRIER_WAIT_PARITY(mbf + (c % 3) * 8, (c / 3) & 1);

        const uint32_t sa = st0 + (c % 3) * G_STAGE_BYTES;
        const uint32_t sw = sa + 16384;

        uint32_t af[2][4][4], bf[2][4][2];
        auto ldfrag = [&](int ks, int p) {
            const int kc2 = ks * 2;
#pragma unroll
            for (int mt = 0; mt < 4; ++mt) {
                const int r = wm * 64 + mt * 16 + (lane & 7) + ((lane >> 3) & 1) * 8;
                const int cc = kc2 + (lane >> 4);
                ldsm_x4(af[p][mt][0], af[p][mt][1], af[p][mt][2], af[p][mt][3],
                        sa + r * 128 + ((cc ^ (r & 7)) << 4));
            }
#pragma unroll
            for (int j = 0; j < 2; ++j) {
                const int r = wn * 32 + (j * 2 + ((lane >> 4) & 1)) * 8 + (lane & 7);
                const int cc = kc2 + ((lane >> 3) & 1);
                uint32_t d0, d1, d2, d3;
                ldsm_x4(d0, d1, d2, d3, sw + r * 128 + ((cc ^ (r & 7)) << 4));
                bf[p][2 * j][0] = d0; bf[p][2 * j][1] = d1;
                bf[p][2 * j + 1][0] = d2; bf[p][2 * j + 1][1] = d3;
            }
        };

        ldfrag(0, 0);
#pragma unroll
        for (int ks = 0; ks < 4; ++ks) {
            if (ks < 3) {
                ldfrag(ks + 1, (ks + 1) & 1);
                if (ks == 2 && lane == 0)
                    MBARRIER_ARRIVE(mbe + (c % 3) * 8);
            }
            const int p = ks & 1;
#pragma unroll
            for (int mt = 0; mt < 4; ++mt)
#pragma unroll
                for (int nt = 0; nt < 4; ++nt)
                    mma_f16(acc[mt][nt], af[p][mt][0], af[p][mt][1], af[p][mt][2], af[p][mt][3],
                            bf[p][nt][0], bf[p][nt][1]);
        }

        if (tid == 0 && c + 3 < G_NCH) {
            MBARRIER_WAIT_PARITY(mbe + (c % 3) * 8, (c / 3) & 1);
            produce(c + 3);
        }
    }

    // Epilogue
#pragma unroll
    for (int mt = 0; mt < 4; ++mt) {
#pragma unroll
        for (int nt = 0; nt < 4; ++nt) {
            const int r0 = m0 + wm * 64 + mt * 16 + g;
            const int col = n0 + wn * 32 + nt * 8 + 2 * t;
            if (MODE == 0) {
                *(float2*)(C + (size_t)r0 * EE + col) =
                    make_float2(acc[mt][nt][0], acc[mt][nt][1]);
                *(float2*)(C + (size_t)(r0 + 8) * EE + col) =
                    make_float2(acc[mt][nt][2], acc[mt][nt][3]);
            } else {
                const int which = col >> 10;
                const int rem = col & 1023;
                const int h = rem >> 6;
                const int d = rem & 63;
#pragma unroll
                for (int half = 0; half < 2; ++half) {
                    const int row = r0 + half * 8;
                    const float v0 = acc[mt][nt][2 * half];
                    const float v1 = acc[mt][nt][2 * half + 1];
                    const int bh = (row >> 11) * HH + h;
                    const int tt = row & 2047;
                    if (which == 0) {
                        *(uint32_t*)(g_qh + ((size_t)bh * TT + tt) * DD + d) =
                            f2h2(v0 * QSCALE, v1 * QSCALE);
                    } else if (which == 1) {
                        *(uint32_t*)(g_kh + ((size_t)bh * TT + tt) * DD + d) =
                            f2h2(v0, v1);
                    } else {
                        g_vth[((size_t)bh * DD + d) * TT + tt]     = __float2half(v0);
                        g_vth[((size_t)bh * DD + d + 1) * TT + tt] = __float2half(v1);
                    }
                }
            }
        }
    }
}

// ---------------------------------------------------------------------------
// Causal flash attention (fp16 mma, fp32 accum): q-tile 128, kv-tile 64,
// 8 warps (warp owns 16 rows). P roundtrips through SMEM (R8-proven path).
// Q fragments hoisted to registers once. TMA SW128, 3-stage kv full/empty
// pipeline, no block syncs in mainloop, 2 CTAs/SM. Softmax in log2 domain.
// SMEM (from aligned base):
//   0      : barriers (q_full @0, kv_full @8..31, kv_empty @32..55)
//   1024   : Q   (128 x 128B = 16KB)
//   17408  : P   (128 x 128B = 16KB)
//   33792  : K/VT stages (3 x 16KB: K 8KB + VT 8KB each)
// ---------------------------------------------------------------------------
#define FA_Q_OFF   1024
#define FA_P_OFF   (FA_Q_OFF + 16384)
#define FA_KV_OFF  (FA_P_OFF + 16384)
#define FA_SMEM_BYTES (FA_KV_OFF + 3 * 16384 + 1024)

__global__ __launch_bounds__(256, 2)
void flash_attn_tma(const __grid_constant__ CUtensorMap tmQ,
                    const __grid_constant__ CUtensorMap tmK,
                    const __grid_constant__ CUtensorMap tmVT)
{
    extern __shared__ char smraw[];
    uint32_t sb = smem_u32(smraw);
    sb = (sb + 1023u) & ~1023u;

    const int qt = gridDim.x - 1 - blockIdx.x;   // long tiles first
    const int bh = blockIdx.y;
    const int q0 = qt * 128;

    const int tid = threadIdx.x, lane = tid & 31, wid = tid >> 5;
    const int g = lane >> 2, t = lane & 3;
    const int wrow = wid * 16;

    const uint32_t qb  = sb + FA_Q_OFF;
    const uint32_t pb  = sb + FA_P_OFF;
    const uint32_t kvb = sb + FA_KV_OFF;
    const uint32_t mbf = sb + 8;    // kv full @ 8,16,24
    const uint32_t mbe = sb + 32;   // kv empty @ 32,40,48

    if (tid == 0) {
        MBARRIER_INIT(sb + 0, 1);
#pragma unroll
        for (int s = 0; s < 3; ++s) {
            MBARRIER_INIT(mbf + s * 8, 1);
            MBARRIER_INIT(mbe + s * 8, 8);
        }
    }
    __syncthreads();

    auto produce_kv = [&](int kt) {
        const int s = kt % 3;
        const int k0 = kt * 64;
        MBARRIER_EXPECT_TX(mbf + s * 8, 16384);
        TMA_LOAD_2D(kvb + s * 16384,        &tmK,  0,  bh * TT + k0, mbf + s * 8);
        TMA_LOAD_2D(kvb + s * 16384 + 8192, &tmVT, k0, bh * 64,      mbf + s * 8);
    };

    const int ktmax = 2 * qt + 1;
    if (tid == 0) {
        MBARRIER_EXPECT_TX(sb + 0, 16384);
        TMA_LOAD_2D(qb, &tmQ, 0, bh * TT + q0, sb + 0);
        produce_kv(0);
        produce_kv(1);
        produce_kv(2);
    }
    MBARRIER_WAIT_PARITY(sb + 0, 0);

    // Hoist Q fragments (constant across kv tiles)
    uint32_t qa[4][4];
#pragma unroll
    for (int ks = 0; ks < 4; ++ks) {
        const int r = wrow + (lane & 7) + ((lane >> 3) & 1) * 8;
        const int cc = ks * 2 + (lane >> 4);
        ldsm_x4(qa[ks][0], qa[ks][1], qa[ks][2], qa[ks][3],
                qb + r * 128 + ((cc ^ (r & 7)) << 4));
    }

    float o[8][4];
#pragma unroll
    for (int nt = 0; nt < 8; ++nt)
#pragma unroll
        for (int j = 0; j < 4; ++j) o[nt][j] = 0.f;
    float mr0 = -INFINITY, mr1 = -INFINITY, lr0 = 0.f, lr1 = 0.f;

    for (int kt = 0; kt <= ktmax; ++kt) {
        const int s3 = kt % 3;
        const int ph = (kt / 3) & 1;
        MBARRIER_WAIT_PARITY(mbf + s3 * 8, ph);

        const int k0 = kt * 64;
        const bool active = (k0 <= q0 + wrow + 15);

        if (active) {
            const uint32_t ks_b = kvb + s3 * 16384;
            const uint32_t vt_b = ks_b + 8192;

            // --- S = Q K^T (Q from registers) ---
            float s[8][4];
#pragma unroll
            for (int nt = 0; nt < 8; ++nt)
#pragma unroll
                for (int j = 0; j < 4; ++j) s[nt][j] = 0.f;

#pragma unroll
            for (int ks = 0; ks < 4; ++ks) {
                const int kc2 = ks * 2;
                uint32_t b[8][2];
#pragma unroll
                for (int j = 0; j < 4; ++j) {
                    const int r = (j * 2 + ((lane >> 4) & 1)) * 8 + (lane & 7);
                    const int cc = kc2 + ((lane >> 3) & 1);
                    uint32_t d0, d1, d2, d3;
                    ldsm_x4(d0, d1, d2, d3, ks_b + r * 128 + ((cc ^ (r & 7)) << 4));
                    b[2 * j][0] = d0; b[2 * j][1] = d1;
                    b[2 * j + 1][0] = d2; b[2 * j + 1][1] = d3;
                }
#pragma unroll
                for (int nt = 0; nt < 8; ++nt)
                    mma_f16(s[nt], qa[ks][0], qa[ks][1], qa[ks][2], qa[ks][3],
                            b[nt][0], b[nt][1]);
            }

            // --- causal mask (diagonal region only) ---
            if (k0 + 63 > q0 + wrow) {
                const int rlo = q0 + wrow + g;
#pragma unroll
                for (int nt = 0; nt < 8; ++nt) {
                    const int key = k0 + nt * 8 + 2 * t;
                    if (key > rlo)         s[nt][0] = -INFINITY;
                    if (key + 1 > rlo)     s[nt][1] = -INFINITY;
                    if (key > rlo + 8)     s[nt][2] = -INFINITY;
                    if (key + 1 > rlo + 8) s[nt][3] = -INFINITY;
                }
            }

            // --- online softmax (log2 domain) + P store (fp16, swizzled) ---
            float mx0 = -INFINITY, mx1 = -INFINITY;
#pragma unroll
            for (int nt = 0; nt < 8; ++nt) {
                mx0 = fmaxf(mx0, fmaxf(s[nt][0], s[nt][1]));
                mx1 = fmaxf(mx1, fmaxf(s[nt][2], s[nt][3]));
            }
            mx0 = fmaxf(mx0, __shfl_xor_sync(0xffffffffu, mx0, 1));
            mx0 = fmaxf(mx0, __shfl_xor_sync(0xffffffffu, mx0, 2));
            mx1 = fmaxf(mx1, __shfl_xor_sync(0xffffffffu, mx1, 1));
            mx1 = fmaxf(mx1, __shfl_xor_sync(0xffffffffu, mx1, 2));

            const float mn0 = fmaxf(mr0, mx0);
            const float mn1 = fmaxf(mr1, mx1);
            const float al0 = ex2f(mr0 - mn0);
            const float al1 = ex2f(mr1 - mn1);
            mr0 = mn0; mr1 = mn1;

            float s0 = 0.f, s1 = 0.f;
#pragma unroll
            for (int nt = 0; nt < 8; ++nt) {
                s[nt][0] = ex2f(s[nt][0] - mn0);
                s[nt][1] = ex2f(s[nt][1] - mn0);
                s[nt][2] = ex2f(s[nt][2] - mn1);
                s[nt][3] = ex2f(s[nt][3] - mn1);
                s0 += s[nt][0] + s[nt][1];
                s1 += s[nt][2] + s[nt][3];
            }
            s0 += __shfl_xor_sync(0xffffffffu, s0, 1);
            s0 += __shfl_xor_sync(0xffffffffu, s0, 2);
            s1 += __shfl_xor_sync(0xffffffffu, s1, 1);
            s1 += __shfl_xor_sync(0xffffffffu, s1, 2);

            lr0 = lr0 * al0 + s0;
            lr1 = lr1 * al1 + s1;
#pragma unroll
            for (int nt = 0; nt < 8; ++nt) {
                o[nt][0] *= al0; o[nt][1] *= al0;
                o[nt][2] *= al1; o[nt][3] *= al1;
            }

#pragma unroll
            for (int half = 0; half < 2; ++half) {
                const int pr = wrow + g + half * 8;
#pragma unroll
                for (int nt = 0; nt < 8; ++nt) {
                    const uint32_t addr = pb + pr * 128 +
                                          ((nt ^ (pr & 7)) << 4) + 4 * t;
                    const uint32_t val = f2h2(s[nt][2 * half], s[nt][2 * half + 1]);
                    asm volatile("st.shared.b32 [%0], %1;"
                                 :: "r"(addr), "r"(val) : "memory");
                }
            }
            __syncwarp();

            // --- O += P V (P from SMEM, R8-proven path) ---
#pragma unroll
            for (int ks = 0; ks < 4; ++ks) {
                const int kc2 = ks * 2;
                uint32_t a[4];
                {
                    const int r = wrow + (lane & 7) + ((lane >> 3) & 1) * 8;
                    const int cc = kc2 + (lane >> 4);
                    ldsm_x4(a[0], a[1], a[2], a[3],
                            pb + r * 128 + ((cc ^ (r & 7)) << 4));
                }
                uint32_t b[8][2];
#pragma unroll
                for (int j = 0; j < 4; ++j) {
                    const int r = (j * 2 + ((lane >> 4) & 1)) * 8 + (lane & 7);
                    const int cc = kc2 + ((lane >> 3) & 1);
                    uint32_t d0, d1, d2, d3;
                    ldsm_x4(d0, d1, d2, d3, vt_b + r * 128 + ((cc ^ (r & 7)) << 4));
                    b[2 * j][0] = d0; b[2 * j][1] = d1;
                    b[2 * j + 1][0] = d2; b[2 * j + 1][1] = d3;
                }
#pragma unroll
                for (int nt = 0; nt < 8; ++nt)
                    mma_f16(o[nt], a[0], a[1], a[2], a[3], b[nt][0], b[nt][1]);
            }
        }

        if (lane == 0) MBARRIER_ARRIVE(mbe + s3 * 8);

        if (tid == 0 && kt + 3 <= ktmax) {
            MBARRIER_WAIT_PARITY(mbe + s3 * 8, ph);
            produce_kv(kt + 3);
        }
    }

    // --- epilogue: normalize, write fp16 att [B,T,E] ---
    const int b = bh >> 4, h = bh & 15;
#pragma unroll
    for (int half = 0; half < 2; ++half) {
        const int row = q0 + wrow + g + half * 8;
        const float inv = 1.0f / (half ? lr1 : lr0);
#pragma unroll
        for (int nt = 0; nt < 8; ++nt) {
            const int col = h * 64 + nt * 8 + 2 * t;
            *(uint32_t*)(g_atth + ((size_t)b * TT + row) * EE + col) =
                f2h2(o[nt][2 * half] * inv, o[nt][2 * half + 1] * inv);
        }
    }
}

// ---------------------------------------------------------------------------
// Host
// ---------------------------------------------------------------------------
typedef CUresult (*EncodeFn)(CUtensorMap*, CUtensorMapDataType, cuuint32_t, void*,
                             const cuuint64_t*, const cuuint64_t*, const cuuint32_t*,
                             const cuuint32_t*, CUtensorMapInterleave, CUtensorMapSwizzle,
                             CUtensorMapL2promotion, CUtensorMapFloatOOBfill);

static void make_tm(EncodeFn enc, CUtensorMap* tm, void* ptr,
                    uint64_t d0, uint64_t d1, uint32_t b0, uint32_t b1)
{
    cuuint64_t dims[2]    = {d0, d1};
    cuuint64_t strides[1] = {d0 * 2};
    cuuint32_t box[2]     = {b0, b1};
    cuuint32_t estr[2]    = {1, 1};
    enc(tm, CU_TENSOR_MAP_DATA_TYPE_FLOAT16, 2, ptr, dims, strides, box, estr,
        CU_TENSOR_MAP_INTERLEAVE_NONE, CU_TENSOR_MAP_SWIZZLE_128B,
        CU_TENSOR_MAP_L2_PROMOTION_L2_128B, CU_TENSOR_MAP_FLOAT_OOB_FILL_NONE);
}

extern "C" void kernel_launch(void* const* d_in, const int* in_sizes, int n_in,
                              void* d_out, int out_size)
{
    const float* x    = (const float*)d_in[0];   // [B,T,E]
    const float* Wqkv = (const float*)d_in[1];   // [3E,E]
    const float* Wout = (const float*)d_in[2];   // [E,E]
    float* out = (float*)d_out;                  // [B,T,E]

    void *xh, *wqkvh, *wouth, *atth, *qp, *kp, *vtp;
    cudaGetSymbolAddress(&xh, g_xh);
    cudaGetSymbolAddress(&wqkvh, g_wqkvh);
    cudaGetSymbolAddress(&wouth, g_wouth);
    cudaGetSymbolAddress(&atth, g_atth);
    cudaGetSymbolAddress(&qp, g_qh);
    cudaGetSymbolAddress(&kp, g_kh);
    cudaGetSymbolAddress(&vtp, g_vth);

    void* pf = nullptr;
    cudaDriverEntryPointQueryResult qr;
    cudaGetDriverEntryPoint("cuTensorMapEncodeTiled", &pf, cudaEnableDefault, &qr);
    EncodeFn enc = (EncodeFn)pf;

    CUtensorMap tmX, tmWqkv, tmAtt, tmWout, tmQ, tmK, tmVT;
    make_tm(enc, &tmX,    xh,    1024, MROWS,               64, 128);
    make_tm(enc, &tmWqkv, wqkvh, 1024, 3072,                64, 128);
    make_tm(enc, &tmAtt,  atth,  1024, MROWS,               64, 128);
    make_tm(enc, &tmWout, wouth, 1024, 1024,                64, 128);
    make_tm(enc, &tmQ,    qp,    64,   (uint64_t)BB * HH * TT, 64, 128);
    make_tm(enc, &tmK,    kp,    64,   (uint64_t)BB * HH * TT, 64, 64);
    make_tm(enc, &tmVT,   vtp,   2048, (uint64_t)BB * HH * DD, 64, 64);

    cudaFuncSetAttribute(gemm_tma<0>, cudaFuncAttributeMaxDynamicSharedMemorySize, GEMM_SMEM_BYTES);
    cudaFuncSetAttribute(gemm_tma<1>, cudaFuncAttributeMaxDynamicSharedMemorySize, GEMM_SMEM_BYTES);
    cudaFuncSetAttribute(flash_attn_tma, cudaFuncAttributeMaxDynamicSharedMemorySize, FA_SMEM_BYTES);

    // 0) convert operands to fp16
    {
        int n4 = MROWS * EE / 4;
        conv_half<<<(n4 + 255) / 256, 256>>>((const float4*)x, (uint2*)xh, n4);
        n4 = 3 * EE * EE / 4;
        conv_half<<<(n4 + 255) / 256, 256>>>((const float4*)Wqkv, (uint2*)wqkvh, n4);
        n4 = EE * EE / 4;
        conv_half<<<(n4 + 255) / 256, 256>>>((const float4*)Wout, (uint2*)wouth, n4);
    }

    // 1) QKV projection + scatter (q scaled, v transposed)
    {
        dim3 grid(3 * EE / 128, MROWS / 128);   // (24, 64)
        gemm_tma<1><<<grid, 256, GEMM_SMEM_BYTES>>>(tmX, tmWqkv, nullptr);
    }

    // 2) Causal flash attention -> g_atth (fp16)
    {
        dim3 grid(TT / 128, BB * HH);           // (16, 64)
        flash_attn_tma<<<grid, 256, FA_SMEM_BYTES>>>(tmQ, tmK, tmVT);
    }

    // 3) Output projection (fp32 out)
    {
        dim3 grid(EE / 128, MROWS / 128);       // (8, 64)
        gemm_tma<0><<<grid, 256, GEMM_SMEM_BYTES>>>(tmAtt, tmWout, out);
    }
}